// round 14
// baseline (speedup 1.0000x reference)
#include <cuda_runtime.h>
#include <cuda_bf16.h>
#include <cuda_fp16.h>
#include <math.h>
#include <stdint.h>

// ----------------------------------------------------------------------------
// Model constants
// ----------------------------------------------------------------------------
constexpr int B_    = 2;
constexpr int S_    = 2048;
constexpr int T_    = B_ * S_;        // 4096 tokens
constexpr int H_    = 2048;
constexpr int NH_   = 16;
constexpr int NKV_  = 8;
constexpr int HD_   = 128;
constexpr int I_    = 5632;
constexpr int L_    = 2;
constexpr int VOCAB_= 32000;
constexpr int QKVN_ = (NH_ + 2 * NKV_) * HD_;  // 4096
constexpr int KOFF_ = NH_ * HD_;               // 2048
constexpr int VOFF_ = KOFF_ + NKV_ * HD_;      // 3072

// ----------------------------------------------------------------------------
// Scratch (device globals: allocation-free rule)
// ----------------------------------------------------------------------------
__device__ float          g_h    [(size_t)T_ * H_];
__device__ __nv_bfloat16  g_x    [(size_t)T_ * H_];
__device__ __nv_bfloat16  g_xl   [(size_t)T_ * H_];
__device__ float          g_qkv  [(size_t)T_ * QKVN_];
__device__ __nv_bfloat16  g_attn [(size_t)T_ * H_];
__device__ __nv_bfloat16  g_attnl[(size_t)T_ * H_];
__device__ __nv_bfloat16  g_si   [(size_t)T_ * I_];
__device__ __nv_bfloat16  g_sil  [(size_t)T_ * I_];
__device__ __nv_bfloat16  g_wh   [(size_t)H_ * VOCAB_];  // weight staging (hi / fp16)
__device__ __nv_bfloat16  g_wl   [(size_t)H_ * VOCAB_];  // lo
// flash-attention operands
__device__ __nv_bfloat16  g_qh [(size_t)B_ * NH_  * S_ * HD_];
__device__ __nv_bfloat16  g_ql [(size_t)B_ * NH_  * S_ * HD_];
__device__ __nv_bfloat16  g_kh [(size_t)B_ * NKV_ * S_ * HD_];
__device__ __nv_bfloat16  g_kl [(size_t)B_ * NKV_ * S_ * HD_];
__device__ __nv_bfloat16  g_vth[(size_t)B_ * NKV_ * HD_ * S_];
__device__ __nv_bfloat16  g_vtl[(size_t)B_ * NKV_ * HD_ * S_];

// ----------------------------------------------------------------------------
// helpers
// ----------------------------------------------------------------------------
__device__ __forceinline__ void split_bf16(float v, __nv_bfloat16& hi, __nv_bfloat16& lo) {
    hi = __float2bfloat16(v);
    lo = __float2bfloat16(v - __bfloat162float(hi));
}

__device__ __forceinline__ void split_fp16(float v, __half& hi, __half& lo) {
    hi = __float2half_rn(v);
    lo = __float2half_rn(v - __half2float(hi));
}

__device__ __forceinline__ uint32_t pack_bf16x2(float x, float y) {
    __nv_bfloat162 t = __float22bfloat162_rn(make_float2(x, y));
    uint32_t u; memcpy(&u, &t, 4);
    return u;
}

__device__ __forceinline__ void mma_bf16(float c[4],
                                         uint32_t a0, uint32_t a1, uint32_t a2, uint32_t a3,
                                         uint32_t b0, uint32_t b1)
{
    asm volatile(
        "mma.sync.aligned.m16n8k16.row.col.f32.bf16.bf16.f32 "
        "{%0,%1,%2,%3}, {%4,%5,%6,%7}, {%8,%9}, {%0,%1,%2,%3};\n"
        : "+f"(c[0]), "+f"(c[1]), "+f"(c[2]), "+f"(c[3])
        : "r"(a0), "r"(a1), "r"(a2), "r"(a3), "r"(b0), "r"(b1));
}

__device__ __forceinline__ void mma_fp16(float c[4],
                                         uint32_t a0, uint32_t a1, uint32_t a2, uint32_t a3,
                                         uint32_t b0, uint32_t b1)
{
    asm volatile(
        "mma.sync.aligned.m16n8k16.row.col.f32.f16.f16.f32 "
        "{%0,%1,%2,%3}, {%4,%5,%6,%7}, {%8,%9}, {%0,%1,%2,%3};\n"
        : "+f"(c[0]), "+f"(c[1]), "+f"(c[2]), "+f"(c[3])
        : "r"(a0), "r"(a1), "r"(a2), "r"(a3), "r"(b0), "r"(b1));
}

__device__ __forceinline__ void ldsm4(uint32_t& r0, uint32_t& r1, uint32_t& r2, uint32_t& r3,
                                      uint32_t addr)
{
    asm volatile("ldmatrix.sync.aligned.m8n8.x4.shared.b16 {%0,%1,%2,%3}, [%4];"
                 : "=r"(r0), "=r"(r1), "=r"(r2), "=r"(r3) : "r"(addr));
}

__device__ __forceinline__ void cpa16(uint32_t* smem, const void* g) {
    uint32_t s = (uint32_t)__cvta_generic_to_shared(smem);
    asm volatile("cp.async.cg.shared.global [%0], [%1], 16;\n" :: "r"(s), "l"(g));
}
__device__ __forceinline__ void cp_commit() {
    asm volatile("cp.async.commit_group;\n");
}
template<int N>
__device__ __forceinline__ void cp_wait() {
    asm volatile("cp.async.wait_group %0;\n" :: "n"(N));
}

// ----------------------------------------------------------------------------
// Weight split + transpose: W[K][N] fp32 -> [N][K] bf16 hi/lo (remap supported)
// ----------------------------------------------------------------------------
__global__ void wsplit_t_kernel(const float* __restrict__ W,
                                __nv_bfloat16* __restrict__ th,
                                __nv_bfloat16* __restrict__ tl,
                                int K, int Nsrc, int coff, int rmul, int roff)
{
    __shared__ float tile[32][33];
    const int n0 = blockIdx.x * 32, k0 = blockIdx.y * 32;
    const int tx = threadIdx.x, ty = threadIdx.y;
#pragma unroll
    for (int r = ty; r < 32; r += 8)
        tile[r][tx] = W[(size_t)(k0 + r) * Nsrc + coff + n0 + tx];
    __syncthreads();
#pragma unroll
    for (int r = ty; r < 32; r += 8) {
        float v = tile[tx][r];
        __nv_bfloat16 hi, lo; split_bf16(v, hi, lo);
        size_t row = (size_t)rmul * (n0 + r) + roff;
        size_t idx = row * K + k0 + tx;
        th[idx] = hi;
        tl[idx] = lo;
    }
}

// Weight transpose to SINGLE fp16 with remap: W[K][N] fp32 -> [N'][K] half
__global__ void wsplit_t_fp16_kernel(const float* __restrict__ W,
                                     __half* __restrict__ th,
                                     int K, int Nsrc, int coff, int rmul, int roff)
{
    __shared__ float tile[32][33];
    const int n0 = blockIdx.x * 32, k0 = blockIdx.y * 32;
    const int tx = threadIdx.x, ty = threadIdx.y;
#pragma unroll
    for (int r = ty; r < 32; r += 8)
        tile[r][tx] = W[(size_t)(k0 + r) * Nsrc + coff + n0 + tx];
    __syncthreads();
#pragma unroll
    for (int r = ty; r < 32; r += 8) {
        size_t row = (size_t)rmul * (n0 + r) + roff;
        th[row * K + k0 + tx] = __float2half_rn(tile[tx][r]);
    }
}

// ----------------------------------------------------------------------------
// bf16 2-split 3-MMA GEMM (qkv / o-proj). CTA 64x128, 4 warps, 2 CTAs/SM.
// MODE 0: C = A@B   MODE 1: C = A@B + R
// ----------------------------------------------------------------------------
constexpr int ST_U32  = 12288;              // 48KB per stage (u32 units)
constexpr int TG_SMEM = 2 * ST_U32 * 4;     // 96KB

template<int MODE>
__global__ __launch_bounds__(128, 2)
void tg_kernel(const __nv_bfloat16* __restrict__ Ah, const __nv_bfloat16* __restrict__ Al,
               const __nv_bfloat16* __restrict__ Bh, const __nv_bfloat16* __restrict__ Bl,
               const float* __restrict__ R, float* __restrict__ C,
               int M, int N, int K)
{
    extern __shared__ uint32_t sm[];
    const uint32_t smem_b = (uint32_t)__cvta_generic_to_shared(sm);

    const int tid   = threadIdx.x;
    const int lane  = tid & 31;
    const int warpN = tid >> 5;
    const int g     = lane >> 2;
    const int tg    = lane & 3;
    const int rr    = lane & 7;
    const int ts    = lane >> 3;
    const int bx = blockIdx.x, by = blockIdx.y;

    float acc[4][4][4];
#pragma unroll
    for (int a = 0; a < 4; a++)
#pragma unroll
        for (int b = 0; b < 4; b++)
#pragma unroll
            for (int c = 0; c < 4; c++) acc[a][b][c] = 0.f;

    const int nk = K >> 6;

    auto fill = [&](int kt) {
        uint32_t* base = sm + (kt & 1) * ST_U32;
        const int k0 = kt * 64;
#pragma unroll
        for (int p = 0; p < 4; p++) {
            int i = tid + p * 128;
            int r = i >> 3, c = i & 7;
            int so = r * 32 + ((c ^ (r & 7)) << 2);
            size_t go = (size_t)(by * 64 + r) * K + k0 + c * 8;
            cpa16(base        + so, Ah + go);
            cpa16(base + 2048 + so, Al + go);
        }
#pragma unroll
        for (int p = 0; p < 8; p++) {
            int i = tid + p * 128;
            int r = i >> 3, c = i & 7;
            int so = r * 32 + ((c ^ (r & 7)) << 2);
            size_t go = (size_t)(bx * 128 + r) * K + k0 + c * 8;
            cpa16(base + 4096 + so, Bh + go);
            cpa16(base + 8192 + so, Bl + go);
        }
        cp_commit();
    };

    int mRow[4], nRow[2];
#pragma unroll
    for (int mt = 0; mt < 4; mt++) mRow[mt] = mt * 16 + ((ts & 1) << 3) + rr;
#pragma unroll
    for (int h = 0; h < 2; h++)    nRow[h]  = warpN * 32 + h * 16 + ((ts >> 1) << 3) + rr;
    const int khA = ts >> 1;
    const int khB = ts & 1;

    fill(0);

    for (int kt = 0; kt < nk; kt++) {
        if (kt + 1 < nk) {
            fill(kt + 1);
            cp_wait<1>();
        } else {
            cp_wait<0>();
        }
        __syncthreads();

        const uint32_t stb = smem_b + (uint32_t)(kt & 1) * 49152u;

#pragma unroll
        for (int ks = 0; ks < 4; ks++) {
            uint32_t aFh[4][4], aFl[4][4], bFh[4][2], bFl[4][2];
            const int ca = 2 * ks + khA;
            const int cb = 2 * ks + khB;
#pragma unroll
            for (int mt = 0; mt < 4; mt++) {
                int m = mRow[mt];
                uint32_t off = (uint32_t)(m * 128 + ((ca ^ (m & 7)) << 4));
                ldsm4(aFh[mt][0], aFh[mt][1], aFh[mt][2], aFh[mt][3], stb + off);
                ldsm4(aFl[mt][0], aFl[mt][1], aFl[mt][2], aFl[mt][3], stb + 8192u + off);
            }
#pragma unroll
            for (int h = 0; h < 2; h++) {
                int n = nRow[h];
                uint32_t off = (uint32_t)(n * 128 + ((cb ^ (n & 7)) << 4));
                ldsm4(bFh[2*h][0], bFh[2*h][1], bFh[2*h+1][0], bFh[2*h+1][1],
                      stb + 16384u + off);
                ldsm4(bFl[2*h][0], bFl[2*h][1], bFl[2*h+1][0], bFl[2*h+1][1],
                      stb + 32768u + off);
            }
#pragma unroll
            for (int mt = 0; mt < 4; mt++)
#pragma unroll
                for (int nt = 0; nt < 4; nt++) {
                    mma_bf16(acc[mt][nt], aFh[mt][0], aFh[mt][1], aFh[mt][2], aFh[mt][3],
                             bFh[nt][0], bFh[nt][1]);
                    mma_bf16(acc[mt][nt], aFh[mt][0], aFh[mt][1], aFh[mt][2], aFh[mt][3],
                             bFl[nt][0], bFl[nt][1]);
                    mma_bf16(acc[mt][nt], aFl[mt][0], aFl[mt][1], aFl[mt][2], aFl[mt][3],
                             bFh[nt][0], bFh[nt][1]);
                }
        }
        __syncthreads();
    }

    const size_t rowBase = (size_t)by * 64;
    const int    colBase = bx * 128 + warpN * 32;
#pragma unroll
    for (int mt = 0; mt < 4; mt++) {
        size_t r0 = rowBase + mt * 16 + g;
        size_t r1 = r0 + 8;
#pragma unroll
        for (int nt = 0; nt < 4; nt++) {
            int n = colBase + nt * 8 + 2 * tg;
            size_t i0 = r0 * N + n;
            size_t i1 = r1 * N + n;
            float2 v0 = make_float2(acc[mt][nt][0], acc[mt][nt][1]);
            float2 v1 = make_float2(acc[mt][nt][2], acc[mt][nt][3]);
            if (MODE == 1) {
                float2 q0 = *(const float2*)(R + i0);
                float2 q1 = *(const float2*)(R + i1);
                v0.x += q0.x; v0.y += q0.y;
                v1.x += q1.x; v1.y += q1.y;
            }
            *(float2*)(C + i0) = v0;
            *(float2*)(C + i1) = v1;
        }
    }
}

// ----------------------------------------------------------------------------
// fp16 GEMM: C = A @ B. B single fp16. ASPLIT=2: A = hi+lo (2 MMA, exact A);
// ASPLIT=1: A single fp16 (1 MMA, lm_head).
// CTA 64x128 (validated R12 tile), 4 warps, THREE-stage cp.async ring,
// 96KB smem, 2 CTAs/SM. Each fill gets two compute intervals to land.
// MODE 0: C          MODE 1: C + R
// MODE 2: gate/up interleaved B -> silu(g)*u as fp16 hi/lo, row stride I_.
// MFAST: 1 -> mb=blockIdx.x (M fastest; lm_head DRAM streaming).
// ----------------------------------------------------------------------------
constexpr int STF_U32  = 8192;              // 32KB per stage (u32 units)
constexpr int TGF_SMEM = 3 * STF_U32 * 4;   // 96KB (3 stages)

template<int MODE, int MFAST, int ASPLIT>
__global__ __launch_bounds__(128, 2)
void tgf_kernel(const __half* __restrict__ Ah, const __half* __restrict__ Al,
                const __half* __restrict__ Bf,
                const float* __restrict__ R, float* __restrict__ C,
                __half* __restrict__ oh, __half* __restrict__ ol,
                int M, int N, int K)
{
    extern __shared__ uint32_t sm[];
    const uint32_t smem_b = (uint32_t)__cvta_generic_to_shared(sm);

    const int tid   = threadIdx.x;
    const int lane  = tid & 31;
    const int warpN = tid >> 5;
    const int g     = lane >> 2;
    const int tg    = lane & 3;
    const int rr    = lane & 7;
    const int ts    = lane >> 3;
    const int mb = MFAST ? blockIdx.x : blockIdx.y;
    const int nb = MFAST ? blockIdx.y : blockIdx.x;

    float acc[4][4][4];
#pragma unroll
    for (int a = 0; a < 4; a++)
#pragma unroll
        for (int b = 0; b < 4; b++)
#pragma unroll
            for (int c = 0; c < 4; c++) acc[a][b][c] = 0.f;

    const int nk = K >> 6;

    // per stage (u32): AsH[2048] AsL[2048] Bs[4096]
    auto fill = [&](int kt) {
        uint32_t* base = sm + (kt % 3) * STF_U32;
        const int k0 = kt * 64;
#pragma unroll
        for (int p = 0; p < 4; p++) {
            int i = tid + p * 128;
            int r = i >> 3, c = i & 7;
            int so = r * 32 + ((c ^ (r & 7)) << 2);
            size_t go = (size_t)(mb * 64 + r) * K + k0 + c * 8;
            cpa16(base + so, Ah + go);
            if (ASPLIT == 2) cpa16(base + 2048 + so, Al + go);
        }
#pragma unroll
        for (int p = 0; p < 8; p++) {
            int i = tid + p * 128;
            int r = i >> 3, c = i & 7;
            int so = r * 32 + ((c ^ (r & 7)) << 2);
            size_t go = (size_t)(nb * 128 + r) * K + k0 + c * 8;
            cpa16(base + 4096 + so, Bf + go);
        }
        cp_commit();
    };

    int mRow[4], nRow[2];
#pragma unroll
    for (int mt = 0; mt < 4; mt++) mRow[mt] = mt * 16 + ((ts & 1) << 3) + rr;
#pragma unroll
    for (int h = 0; h < 2; h++)    nRow[h]  = warpN * 32 + h * 16 + ((ts >> 1) << 3) + rr;
    const int khA = ts >> 1;
    const int khB = ts & 1;

    fill(0);
    if (nk > 1) fill(1);

    for (int kt = 0; kt < nk; kt++) {
        if (kt + 2 < nk) {
            fill(kt + 2);
            cp_wait<2>();
        } else {
            cp_wait<0>();
        }
        __syncthreads();

        const uint32_t stb = smem_b + (uint32_t)(kt % 3) * 32768u;

#pragma unroll
        for (int ks = 0; ks < 4; ks++) {
            uint32_t aFh[4][4], aFl[4][4], bF[4][2];
            const int ca = 2 * ks + khA;
            const int cb = 2 * ks + khB;
#pragma unroll
            for (int mt = 0; mt < 4; mt++) {
                int m = mRow[mt];
                uint32_t off = (uint32_t)(m * 128 + ((ca ^ (m & 7)) << 4));
                ldsm4(aFh[mt][0], aFh[mt][1], aFh[mt][2], aFh[mt][3], stb + off);
                if (ASPLIT == 2)
                    ldsm4(aFl[mt][0], aFl[mt][1], aFl[mt][2], aFl[mt][3], stb + 8192u + off);
            }
#pragma unroll
            for (int h = 0; h < 2; h++) {
                int n = nRow[h];
                uint32_t off = (uint32_t)(n * 128 + ((cb ^ (n & 7)) << 4));
                ldsm4(bF[2*h][0], bF[2*h][1], bF[2*h+1][0], bF[2*h+1][1],
                      stb + 16384u + off);
            }
#pragma unroll
            for (int mt = 0; mt < 4; mt++)
#pragma unroll
                for (int nt = 0; nt < 4; nt++) {
                    mma_fp16(acc[mt][nt], aFh[mt][0], aFh[mt][1], aFh[mt][2], aFh[mt][3],
                             bF[nt][0], bF[nt][1]);
                    if (ASPLIT == 2)
                        mma_fp16(acc[mt][nt], aFl[mt][0], aFl[mt][1], aFl[mt][2], aFl[mt][3],
                                 bF[nt][0], bF[nt][1]);
                }
        }
        __syncthreads();
    }

    // ---- epilogue ----
    const size_t rowBase = (size_t)mb * 64;
    const int    colBase = nb * 128 + warpN * 32;
#pragma unroll
    for (int mt = 0; mt < 4; mt++) {
        size_t r0 = rowBase + mt * 16 + g;
        size_t r1 = r0 + 8;
#pragma unroll
        for (int nt = 0; nt < 4; nt++) {
            int n = colBase + nt * 8 + 2 * tg;
            if (MODE == 2) {
                size_t j = (size_t)(n >> 1);     // (gate, up) pair -> col j
                float g0 = acc[mt][nt][0], u0 = acc[mt][nt][1];
                float g1 = acc[mt][nt][2], u1 = acc[mt][nt][3];
                float v0 = g0 / (1.f + __expf(-g0)) * u0;
                float v1 = g1 / (1.f + __expf(-g1)) * u1;
                __half h0, l0, h1, l1;
                split_fp16(v0, h0, l0);
                split_fp16(v1, h1, l1);
                oh[r0 * I_ + j] = h0; ol[r0 * I_ + j] = l0;
                oh[r1 * I_ + j] = h1; ol[r1 * I_ + j] = l1;
            } else {
                size_t i0 = r0 * N + n;
                size_t i1 = r1 * N + n;
                float2 v0 = make_float2(acc[mt][nt][0], acc[mt][nt][1]);
                float2 v1 = make_float2(acc[mt][nt][2], acc[mt][nt][3]);
                if (MODE == 1) {
                    float2 q0 = *(const float2*)(R + i0);
                    float2 q1 = *(const float2*)(R + i1);
                    v0.x += q0.x; v0.y += q0.y;
                    v1.x += q1.x; v1.y += q1.y;
                }
                *(float2*)(C + i0) = v0;
                *(float2*)(C + i1) = v1;
            }
        }
    }
}

// ----------------------------------------------------------------------------
// Embedding gather
// ----------------------------------------------------------------------------
__global__ void embed_kernel(const int* __restrict__ ids,
                             const float* __restrict__ emb,
                             float* __restrict__ h)
{
    int t = blockIdx.x;
    int id = ids[t];
    const float4* src = (const float4*)(emb + (size_t)id * H_);
    float4* dst = (float4*)(h + (size_t)t * H_);
    for (int i = threadIdx.x; i < H_ / 4; i += blockDim.x) dst[i] = src[i];
}

// ----------------------------------------------------------------------------
// RMSNorm -> bf16 (hi, lo)
// ----------------------------------------------------------------------------
__global__ void rmsnorm_kernel(const float* __restrict__ h,
                               const float* __restrict__ w,
                               __nv_bfloat16* __restrict__ xh,
                               __nv_bfloat16* __restrict__ xl)
{
    int t = blockIdx.x;
    const float* hr = h + (size_t)t * H_;
    __shared__ float red[256];
    float s = 0.f;
    for (int i = threadIdx.x; i < H_; i += 256) { float v = hr[i]; s += v * v; }
    red[threadIdx.x] = s; __syncthreads();
    for (int st = 128; st > 0; st >>= 1) {
        if (threadIdx.x < st) red[threadIdx.x] += red[threadIdx.x + st];
        __syncthreads();
    }
    float scale = rsqrtf(red[0] / (float)H_ + 1e-5f);
    for (int i = threadIdx.x; i < H_; i += 256) {
        float v = hr[i] * scale * w[i];
        __nv_bfloat16 hi, lo; split_bf16(v, hi, lo);
        xh[(size_t)t * H_ + i] = hi;
        xl[(size_t)t * H_ + i] = lo;
    }
}

// RMSNorm -> fp16 (hi, lo)
__global__ void rmsnorm_fp16_kernel(const float* __restrict__ h,
                                    const float* __restrict__ w,
                                    __half* __restrict__ xh,
                                    __half* __restrict__ xl)
{
    int t = blockIdx.x;
    const float* hr = h + (size_t)t * H_;
    __shared__ float red[256];
    float s = 0.f;
    for (int i = threadIdx.x; i < H_; i += 256) { float v = hr[i]; s += v * v; }
    red[threadIdx.x] = s; __syncthreads();
    for (int st = 128; st > 0; st >>= 1) {
        if (threadIdx.x < st) red[threadIdx.x] += red[threadIdx.x + st];
        __syncthreads();
    }
    float scale = rsqrtf(red[0] / (float)H_ + 1e-5f);
    for (int i = threadIdx.x; i < H_; i += 256) {
        float v = hr[i] * scale * w[i];
        __half hi, lo; split_fp16(v, hi, lo);
        xh[(size_t)t * H_ + i] = hi;
        xl[(size_t)t * H_ + i] = lo;
    }
}

// ----------------------------------------------------------------------------
// Q/K prep: fused RoPE + Q-scale + bf16 hi/lo split
// ----------------------------------------------------------------------------
__global__ void qkprep_kernel(const float* __restrict__ qkv, const int* __restrict__ pos,
                              __nv_bfloat16* __restrict__ Qh, __nv_bfloat16* __restrict__ Ql,
                              __nv_bfloat16* __restrict__ Kh, __nv_bfloat16* __restrict__ Kl)
{
    int idx = blockIdx.x * blockDim.x + threadIdx.x;
    if (idx >= T_ * 24 * 64) return;
    int i    = idx & 63;
    int head = (idx >> 6) % 24;
    int t    = idx / (24 * 64);
    int b = t / S_, s = t % S_;

    float p = (float)pos[t];
    float e = ((float)i / 64.0f) * 13.28771237954945f;  // log2(10000)
    float inv = exp2f(-e);
    float ang = p * inv;
    float sn, cs;
    sincosf(ang, &sn, &cs);

    int off = (head < NH_) ? head * HD_ : KOFF_ + (head - NH_) * HD_;
    const float* v = qkv + (size_t)t * QKVN_ + off;
    float x1 = v[i], x2 = v[i + 64];
    float r1 = x1 * cs - x2 * sn;
    float r2 = x2 * cs + x1 * sn;

    __nv_bfloat16 *dh, *dl;
    if (head < NH_) {
        const float scale = 0.08838834764831845f;
        r1 *= scale; r2 *= scale;
        size_t base = (((size_t)(b * NH_ + head)) * S_ + s) * HD_;
        dh = Qh + base; dl = Ql + base;
    } else {
        size_t base = (((size_t)(b * NKV_ + head - NH_)) * S_ + s) * HD_;
        dh = Kh + base; dl = Kl + base;
    }
    __nv_bfloat16 h1, l1, h2, l2;
    split_bf16(r1, h1, l1);
    split_bf16(r2, h2, l2);
    dh[i] = h1;      dl[i] = l1;
    dh[i + 64] = h2; dl[i + 64] = l2;
}

// ----------------------------------------------------------------------------
// V prep: transpose to [B][NKV][HD][S] + bf16 hi/lo split
// ----------------------------------------------------------------------------
__global__ void vprep_kernel(const float* __restrict__ qkv,
                             __nv_bfloat16* __restrict__ Vth,
                             __nv_bfloat16* __restrict__ Vtl)
{
    __shared__ float tile[32][33];
    const int z = blockIdx.z;
    const int b = z / NKV_, hkv = z % NKV_;
    const int s0 = blockIdx.x * 32, d0 = blockIdx.y * 32;
    const int tx = threadIdx.x, ty = threadIdx.y;
#pragma unroll
    for (int r = ty; r < 32; r += 8)
        tile[r][tx] = qkv[(size_t)(b * S_ + s0 + r) * QKVN_ + VOFF_ + hkv * HD_ + d0 + tx];
    __syncthreads();
    size_t base = ((size_t)(b * NKV_ + hkv)) * HD_ * S_;
#pragma unroll
    for (int r = ty; r < 32; r += 8) {
        float v = tile[tx][r];
        __nv_bfloat16 hi, lo; split_bf16(v, hi, lo);
        size_t idx = base + (size_t)(d0 + r) * S_ + s0 + tx;
        Vth[idx] = hi;
        Vtl[idx] = lo;
    }
}

// ----------------------------------------------------------------------------
// Flash attention (validated R5 kernel, unchanged)
// ----------------------------------------------------------------------------
__global__ __launch_bounds__(128)
void flash_kernel(const __nv_bfloat16* __restrict__ Qh, const __nv_bfloat16* __restrict__ Ql,
                  const __nv_bfloat16* __restrict__ Kh, const __nv_bfloat16* __restrict__ Kl,
                  const __nv_bfloat16* __restrict__ Vth, const __nv_bfloat16* __restrict__ Vtl,
                  __nv_bfloat16* __restrict__ Oh, __nv_bfloat16* __restrict__ Ol)
{
    extern __shared__ uint32_t sm[];
    uint32_t* KsH = sm;
    uint32_t* KsL = sm + 4096;
    uint32_t* VsH = sm + 8192;
    uint32_t* VsL = sm + 12288;

    const int qt = (int)gridDim.x - 1 - (int)blockIdx.x;
    const int z  = blockIdx.y;
    const int b  = z >> 4, hq = z & 15, hkv = hq >> 1;

    const int tid  = threadIdx.x;
    const int lane = tid & 31;
    const int w    = tid >> 5;
    const int g    = lane >> 2;
    const int tg   = lane & 3;

    uint32_t qFh[8][4], qFl[8][4];
    {
        const uint32_t* qbh = (const uint32_t*)(Qh + (((size_t)(b * NH_ + hq)) * S_ + qt * 64 + w * 16) * HD_);
        const uint32_t* qbl = (const uint32_t*)(Ql + (((size_t)(b * NH_ + hq)) * S_ + qt * 64 + w * 16) * HD_);
#pragma unroll
        for (int ks = 0; ks < 8; ks++) {
            int c = 8 * ks + tg;
            qFh[ks][0] = qbh[g * 64 + c];
            qFh[ks][1] = qbh[(g + 8) * 64 + c];
            qFh[ks][2] = qbh[g * 64 + c + 4];
            qFh[ks][3] = qbh[(g + 8) * 64 + c + 4];
            qFl[ks][0] = qbl[g * 64 + c];
            qFl[ks][1] = qbl[(g + 8) * 64 + c];
            qFl[ks][2] = qbl[g * 64 + c + 4];
            qFl[ks][3] = qbl[(g + 8) * 64 + c + 4];
        }
    }

    float oAcc[16][4];
#pragma unroll
    for (int i = 0; i < 16; i++)
#pragma unroll
        for (int j = 0; j < 4; j++) oAcc[i][j] = 0.f;
    float mA = -1e30f, mB = -1e30f, lA = 0.f, lB = 0.f;

    const __nv_bfloat16* KgH = Kh  + ((size_t)(b * NKV_ + hkv)) * S_ * HD_;
    const __nv_bfloat16* KgL = Kl  + ((size_t)(b * NKV_ + hkv)) * S_ * HD_;
    const __nv_bfloat16* VgH = Vth + ((size_t)(b * NKV_ + hkv)) * HD_ * S_;
    const __nv_bfloat16* VgL = Vtl + ((size_t)(b * NKV_ + hkv)) * HD_ * S_;

    for (int kt = 0; kt <= qt; kt++) {
#pragma unroll
        for (int p = 0; p < 8; p++) {
            int i = tid + p * 128;
            int r = i >> 4, cc = i & 15;
            int dst = r * 64 + ((cc ^ (r & 7)) << 2);
            cpa16(KsH + dst, KgH + (size_t)(kt * 64 + r) * HD_ + cc * 8);
            cpa16(KsL + dst, KgL + (size_t)(kt * 64 + r) * HD_ + cc * 8);
        }
#pragma unroll
        for (int p = 0; p < 8; p++) {
            int i = tid + p * 128;
            int n = i >> 3, cc = i & 7;
            int dst = n * 32 + ((cc ^ (n & 7)) << 2);
            cpa16(VsH + dst, VgH + (size_t)n * S_ + kt * 64 + cc * 8);
            cpa16(VsL + dst, VgL + (size_t)n * S_ + kt * 64 + cc * 8);
        }
        cp_commit();
        cp_wait<0>();
        __syncthreads();

        float sAcc[8][4];
#pragma unroll
        for (int i = 0; i < 8; i++)
#pragma unroll
            for (int j = 0; j < 4; j++) sAcc[i][j] = 0.f;

#pragma unroll
        for (int ks = 0; ks < 8; ks++) {
            uint32_t kFh[8][2], kFl[8][2];
            const int c0 = 8 * ks + tg;
#pragma unroll
            for (int nt = 0; nt < 8; nt++) {
                int key = nt * 8 + g;
                int sw = (key & 7) << 2;
                int o0 = key * 64 + (c0 ^ sw);
                int o1 = key * 64 + ((c0 + 4) ^ sw);
                kFh[nt][0] = KsH[o0]; kFh[nt][1] = KsH[o1];
                kFl[nt][0] = KsL[o0]; kFl[nt][1] = KsL[o1];
            }
#pragma unroll
            for (int nt = 0; nt < 8; nt++) {
                mma_bf16(sAcc[nt], qFh[ks][0], qFh[ks][1], qFh[ks][2], qFh[ks][3],
                         kFh[nt][0], kFh[nt][1]);
                mma_bf16(sAcc[nt], qFh[ks][0], qFh[ks][1], qFh[ks][2], qFh[ks][3],
                         kFl[nt][0], kFl[nt][1]);
                mma_bf16(sAcc[nt], qFl[ks][0], qFl[ks][1], qFl[ks][2], qFl[ks][3],
                         kFh[nt][0], kFh[nt][1]);
            }
        }

        if (kt == qt) {
            const int qrA = w * 16 + g, qrB = qrA + 8;
#pragma unroll
            for (int nt = 0; nt < 8; nt++) {
                int k0 = nt * 8 + 2 * tg, k1 = k0 + 1;
                if (k0 > qrA) sAcc[nt][0] = -1e30f;
                if (k1 > qrA) sAcc[nt][1] = -1e30f;
                if (k0 > qrB) sAcc[nt][2] = -1e30f;
                if (k1 > qrB) sAcc[nt][3] = -1e30f;
            }
        }

        float tmA = -1e30f, tmB = -1e30f;
#pragma unroll
        for (int nt = 0; nt < 8; nt++) {
            tmA = fmaxf(tmA, fmaxf(sAcc[nt][0], sAcc[nt][1]));
            tmB = fmaxf(tmB, fmaxf(sAcc[nt][2], sAcc[nt][3]));
        }
        tmA = fmaxf(tmA, __shfl_xor_sync(0xffffffff, tmA, 1));
        tmA = fmaxf(tmA, __shfl_xor_sync(0xffffffff, tmA, 2));
        tmB = fmaxf(tmB, __shfl_xor_sync(0xffffffff, tmB, 1));
        tmB = fmaxf(tmB, __shfl_xor_sync(0xffffffff, tmB, 2));
        float nmA = fmaxf(mA, tmA), nmB = fmaxf(mB, tmB);
        float eA = __expf(mA - nmA), eB = __expf(mB - nmB);

        float rsA = 0.f, rsB = 0.f;
#pragma unroll
        for (int nt = 0; nt < 8; nt++) {
            sAcc[nt][0] = __expf(sAcc[nt][0] - nmA);
            sAcc[nt][1] = __expf(sAcc[nt][1] - nmA);
            sAcc[nt][2] = __expf(sAcc[nt][2] - nmB);
            sAcc[nt][3] = __expf(sAcc[nt][3] - nmB);
            rsA += sAcc[nt][0] + sAcc[nt][1];
            rsB += sAcc[nt][2] + sAcc[nt][3];
        }
        rsA += __shfl_xor_sync(0xffffffff, rsA, 1);
        rsA += __shfl_xor_sync(0xffffffff, rsA, 2);
        rsB += __shfl_xor_sync(0xffffffff, rsB, 1);
        rsB += __shfl_xor_sync(0xffffffff, rsB, 2);
        lA = lA * eA + rsA;
        lB = lB * eB + rsB;
        mA = nmA; mB = nmB;
#pragma unroll
        for (int nt = 0; nt < 16; nt++) {
            oAcc[nt][0] *= eA; oAcc[nt][1] *= eA;
            oAcc[nt][2] *= eB; oAcc[nt][3] *= eB;
        }

#pragma unroll
        for (int ks2 = 0; ks2 < 4; ks2++) {
            uint32_t ph[4], pl[4];
#pragma unroll
            for (int q = 0; q < 2; q++) {
                const float* s4 = sAcc[2 * ks2 + q];
                uint32_t hp0 = pack_bf16x2(s4[0], s4[1]);
                uint32_t hp1 = pack_bf16x2(s4[2], s4[3]);
                float h00 = __uint_as_float(hp0 << 16);
                float h01 = __uint_as_float(hp0 & 0xFFFF0000u);
                float h10 = __uint_as_float(hp1 << 16);
                float h11 = __uint_as_float(hp1 & 0xFFFF0000u);
                ph[2 * q]     = hp0;
                ph[2 * q + 1] = hp1;
                pl[2 * q]     = pack_bf16x2(s4[0] - h00, s4[1] - h01);
                pl[2 * q + 1] = pack_bf16x2(s4[2] - h10, s4[3] - h11);
            }
            const int kp = 8 * ks2 + tg;
#pragma unroll
            for (int nt2 = 0; nt2 < 16; nt2++) {
                int n = nt2 * 8 + g;
                int sw = (n & 7) << 2;
                int o0 = n * 32 + (kp ^ sw);
                int o1 = n * 32 + ((kp + 4) ^ sw);
                uint32_t v0h = VsH[o0], v1h = VsH[o1];
                uint32_t v0l = VsL[o0], v1l = VsL[o1];
                mma_bf16(oAcc[nt2], ph[0], ph[1], ph[2], ph[3], v0h, v1h);
                mma_bf16(oAcc[nt2], ph[0], ph[1], ph[2], ph[3], v0l, v1l);
                mma_bf16(oAcc[nt2], pl[0], pl[1], pl[2], pl[3], v0h, v1h);
            }
        }
        __syncthreads();
    }

    const float ilA = 1.f / lA, ilB = 1.f / lB;
    const size_t tA = (size_t)b * S_ + qt * 64 + w * 16 + g;
    const size_t tB = tA + 8;
#pragma unroll
    for (int nt2 = 0; nt2 < 16; nt2++) {
        int col = hq * HD_ + nt2 * 8 + 2 * tg;
        float a0 = oAcc[nt2][0] * ilA, a1 = oAcc[nt2][1] * ilA;
        float b0 = oAcc[nt2][2] * ilB, b1 = oAcc[nt2][3] * ilB;

        uint32_t ahp = pack_bf16x2(a0, a1);
        uint32_t bhp = pack_bf16x2(b0, b1);
        float ah0 = __uint_as_float(ahp << 16), ah1 = __uint_as_float(ahp & 0xFFFF0000u);
        float bh0 = __uint_as_float(bhp << 16), bh1 = __uint_as_float(bhp & 0xFFFF0000u);
        uint32_t alp = pack_bf16x2(a0 - ah0, a1 - ah1);
        uint32_t blp = pack_bf16x2(b0 - bh0, b1 - bh1);

        *(uint32_t*)(Oh + tA * H_ + col) = ahp;
        *(uint32_t*)(Ol + tA * H_ + col) = alp;
        *(uint32_t*)(Oh + tB * H_ + col) = bhp;
        *(uint32_t*)(Ol + tB * H_ + col) = blp;
    }
}

// ----------------------------------------------------------------------------
// Host orchestration
// ----------------------------------------------------------------------------
extern "C" void kernel_launch(void* const* d_in, const int* in_sizes, int n_in,
                              void* d_out, int out_size)
{
    (void)in_sizes; (void)n_in; (void)out_size;
    const int*   ids    = (const int*)  d_in[0];
    const int*   pos    = (const int*)  d_in[1];
    const float* emb    = (const float*)d_in[2];
    const float* Wqkv   = (const float*)d_in[3];
    const float* Wo     = (const float*)d_in[4];
    const float* Wgu    = (const float*)d_in[5];
    const float* Wdn    = (const float*)d_in[6];
    const float* ln1    = (const float*)d_in[7];
    const float* ln2    = (const float*)d_in[8];
    const float* normw  = (const float*)d_in[9];
    const float* lmhead = (const float*)d_in[10];
    float* out = (float*)d_out;

    cudaFuncSetAttribute(tg_kernel<0>, cudaFuncAttributeMaxDynamicSharedMemorySize, TG_SMEM);
    cudaFuncSetAttribute(tg_kernel<1>, cudaFuncAttributeMaxDynamicSharedMemorySize, TG_SMEM);
    cudaFuncSetAttribute((const void*)tgf_kernel<0,1,1>, cudaFuncAttributeMaxDynamicSharedMemorySize, TGF_SMEM);
    cudaFuncSetAttribute((const void*)tgf_kernel<1,0,2>, cudaFuncAttributeMaxDynamicSharedMemorySize, TGF_SMEM);
    cudaFuncSetAttribute((const void*)tgf_kernel<2,0,2>, cudaFuncAttributeMaxDynamicSharedMemorySize, TGF_SMEM);
    cudaFuncSetAttribute(flash_kernel, cudaFuncAttributeMaxDynamicSharedMemorySize, 65536);

    float *h, *qkv;
    __nv_bfloat16 *x, *xl, *attn, *attnl, *si, *sil, *wh, *wl;
    __nv_bfloat16 *qh, *ql, *kh, *kl, *vth, *vtl;
    cudaGetSymbolAddress((void**)&h,     g_h);
    cudaGetSymbolAddress((void**)&x,     g_x);
    cudaGetSymbolAddress((void**)&xl,    g_xl);
    cudaGetSymbolAddress((void**)&qkv,   g_qkv);
    cudaGetSymbolAddress((void**)&attn,  g_attn);
    cudaGetSymbolAddress((void**)&attnl, g_attnl);
    cudaGetSymbolAddress((void**)&si,    g_si);
    cudaGetSymbolAddress((void**)&sil,   g_sil);
    cudaGetSymbolAddress((void**)&wh,    g_wh);
    cudaGetSymbolAddress((void**)&wl,    g_wl);
    cudaGetSymbolAddress((void**)&qh,    g_qh);
    cudaGetSymbolAddress((void**)&ql,    g_ql);
    cudaGetSymbolAddress((void**)&kh,    g_kh);
    cudaGetSymbolAddress((void**)&kl,    g_kl);
    cudaGetSymbolAddress((void**)&vth,   g_vth);
    cudaGetSymbolAddress((void**)&vtl,   g_vtl);

    embed_kernel<<<T_, 256>>>(ids, emb, h);

    for (int l = 0; l < L_; l++) {
        const float* wqkv = Wqkv + (size_t)l * H_ * QKVN_;
        const float* wo   = Wo   + (size_t)l * H_ * H_;
        const float* wgu  = Wgu  + (size_t)l * H_ * (2 * I_);
        const float* wdn  = Wdn  + (size_t)l * I_ * H_;

        // ---- attention block (bf16 3-MMA, validated) ----
        rmsnorm_kernel<<<T_, 256>>>(h, ln1 + (size_t)l * H_, x, xl);
        wsplit_t_kernel<<<dim3(QKVN_ / 32, H_ / 32), dim3(32, 8)>>>(wqkv, wh, wl, H_, QKVN_, 0, 1, 0);
        tg_kernel<0><<<dim3(QKVN_ / 128, T_ / 64), 128, TG_SMEM>>>(x, xl, wh, wl, nullptr, qkv,
                                                                   T_, QKVN_, H_);

        {
            int tot = T_ * 24 * 64;
            qkprep_kernel<<<(tot + 255) / 256, 256>>>(qkv, pos, qh, ql, kh, kl);
        }
        vprep_kernel<<<dim3(S_ / 32, HD_ / 32, B_ * NKV_), dim3(32, 8)>>>(qkv, vth, vtl);

        flash_kernel<<<dim3(S_ / 64, B_ * NH_), 128, 65536>>>(qh, ql, kh, kl, vth, vtl,
                                                              attn, attnl);

        wsplit_t_kernel<<<dim3(H_ / 32, H_ / 32), dim3(32, 8)>>>(wo, wh, wl, H_, H_, 0, 1, 0);
        tg_kernel<1><<<dim3(H_ / 128, T_ / 64), 128, TG_SMEM>>>(attn, attnl, wh, wl, h, h,
                                                                T_, H_, H_);

        // ---- MLP block (fp16 2-MMA, 64x128 tile, 3-stage) ----
        rmsnorm_fp16_kernel<<<T_, 256>>>(h, ln2 + (size_t)l * H_, (__half*)x, (__half*)xl);
        wsplit_t_fp16_kernel<<<dim3(I_ / 32, H_ / 32), dim3(32, 8)>>>(wgu, (__half*)wh,
                                                                      H_, 2 * I_, 0, 2, 0);
        wsplit_t_fp16_kernel<<<dim3(I_ / 32, H_ / 32), dim3(32, 8)>>>(wgu, (__half*)wh,
                                                                      H_, 2 * I_, I_, 2, 1);
        tgf_kernel<2, 0, 2><<<dim3(2 * I_ / 128, T_ / 64), 128, TGF_SMEM>>>(
            (const __half*)x, (const __half*)xl, (const __half*)wh,
            nullptr, nullptr, (__half*)si, (__half*)sil, T_, 2 * I_, H_);

        wsplit_t_fp16_kernel<<<dim3(H_ / 32, I_ / 32), dim3(32, 8)>>>(wdn, (__half*)wh,
                                                                      I_, H_, 0, 1, 0);
        tgf_kernel<1, 0, 2><<<dim3(H_ / 128, T_ / 64), 128, TGF_SMEM>>>(
            (const __half*)si, (const __half*)sil, (const __half*)wh,
            h, h, nullptr, nullptr, T_, H_, I_);
    }

    // ---- final norm + fully-fp16 1-MMA lm_head (M-fastest: stream 128MB B once) ----
    rmsnorm_fp16_kernel<<<T_, 256>>>(h, normw, (__half*)x, (__half*)xl);
    wsplit_t_fp16_kernel<<<dim3(VOCAB_ / 32, H_ / 32), dim3(32, 8)>>>(lmhead, (__half*)wh,
                                                                      H_, VOCAB_, 0, 1, 0);
    tgf_kernel<0, 1, 1><<<dim3(T_ / 64, VOCAB_ / 128), 128, TGF_SMEM>>>(
        (const __half*)x, (const __half*)xl, (const __half*)wh,
        nullptr, out, nullptr, nullptr, T_, VOCAB_, H_);
}

// round 15
// speedup vs baseline: 1.1765x; 1.1765x over previous
#include <cuda_runtime.h>
#include <cuda_bf16.h>
#include <cuda_fp16.h>
#include <math.h>
#include <stdint.h>

// ----------------------------------------------------------------------------
// Model constants
// ----------------------------------------------------------------------------
constexpr int B_    = 2;
constexpr int S_    = 2048;
constexpr int T_    = B_ * S_;        // 4096 tokens
constexpr int H_    = 2048;
constexpr int NH_   = 16;
constexpr int NKV_  = 8;
constexpr int HD_   = 128;
constexpr int I_    = 5632;
constexpr int L_    = 2;
constexpr int VOCAB_= 32000;
constexpr int QKVN_ = (NH_ + 2 * NKV_) * HD_;  // 4096
constexpr int KOFF_ = NH_ * HD_;               // 2048
constexpr int VOFF_ = KOFF_ + NKV_ * HD_;      // 3072

// ----------------------------------------------------------------------------
// Scratch (device globals: allocation-free rule)
// ----------------------------------------------------------------------------
__device__ float          g_h    [(size_t)T_ * H_];
__device__ __nv_bfloat16  g_x    [(size_t)T_ * H_];
__device__ __nv_bfloat16  g_xl   [(size_t)T_ * H_];
__device__ float          g_qkv  [(size_t)T_ * QKVN_];
__device__ __nv_bfloat16  g_attn [(size_t)T_ * H_];
__device__ __nv_bfloat16  g_attnl[(size_t)T_ * H_];
__device__ __nv_bfloat16  g_si   [(size_t)T_ * I_];
__device__ __nv_bfloat16  g_sil  [(size_t)T_ * I_];   // unused by fp16 path, kept for layout
__device__ __nv_bfloat16  g_wh   [(size_t)H_ * VOCAB_];  // weight staging (hi / fp16)
__device__ __nv_bfloat16  g_wl   [(size_t)H_ * VOCAB_];  // lo
// flash-attention operands
__device__ __nv_bfloat16  g_qh [(size_t)B_ * NH_  * S_ * HD_];
__device__ __nv_bfloat16  g_ql [(size_t)B_ * NH_  * S_ * HD_];
__device__ __nv_bfloat16  g_kh [(size_t)B_ * NKV_ * S_ * HD_];
__device__ __nv_bfloat16  g_kl [(size_t)B_ * NKV_ * S_ * HD_];
__device__ __nv_bfloat16  g_vth[(size_t)B_ * NKV_ * HD_ * S_];
__device__ __nv_bfloat16  g_vtl[(size_t)B_ * NKV_ * HD_ * S_];

// ----------------------------------------------------------------------------
// helpers
// ----------------------------------------------------------------------------
__device__ __forceinline__ void split_bf16(float v, __nv_bfloat16& hi, __nv_bfloat16& lo) {
    hi = __float2bfloat16(v);
    lo = __float2bfloat16(v - __bfloat162float(hi));
}

__device__ __forceinline__ void split_fp16(float v, __half& hi, __half& lo) {
    hi = __float2half_rn(v);
    lo = __float2half_rn(v - __half2float(hi));
}

__device__ __forceinline__ uint32_t pack_bf16x2(float x, float y) {
    __nv_bfloat162 t = __float22bfloat162_rn(make_float2(x, y));
    uint32_t u; memcpy(&u, &t, 4);
    return u;
}

__device__ __forceinline__ void mma_bf16(float c[4],
                                         uint32_t a0, uint32_t a1, uint32_t a2, uint32_t a3,
                                         uint32_t b0, uint32_t b1)
{
    asm volatile(
        "mma.sync.aligned.m16n8k16.row.col.f32.bf16.bf16.f32 "
        "{%0,%1,%2,%3}, {%4,%5,%6,%7}, {%8,%9}, {%0,%1,%2,%3};\n"
        : "+f"(c[0]), "+f"(c[1]), "+f"(c[2]), "+f"(c[3])
        : "r"(a0), "r"(a1), "r"(a2), "r"(a3), "r"(b0), "r"(b1));
}

__device__ __forceinline__ void mma_fp16(float c[4],
                                         uint32_t a0, uint32_t a1, uint32_t a2, uint32_t a3,
                                         uint32_t b0, uint32_t b1)
{
    asm volatile(
        "mma.sync.aligned.m16n8k16.row.col.f32.f16.f16.f32 "
        "{%0,%1,%2,%3}, {%4,%5,%6,%7}, {%8,%9}, {%0,%1,%2,%3};\n"
        : "+f"(c[0]), "+f"(c[1]), "+f"(c[2]), "+f"(c[3])
        : "r"(a0), "r"(a1), "r"(a2), "r"(a3), "r"(b0), "r"(b1));
}

__device__ __forceinline__ void ldsm4(uint32_t& r0, uint32_t& r1, uint32_t& r2, uint32_t& r3,
                                      uint32_t addr)
{
    asm volatile("ldmatrix.sync.aligned.m8n8.x4.shared.b16 {%0,%1,%2,%3}, [%4];"
                 : "=r"(r0), "=r"(r1), "=r"(r2), "=r"(r3) : "r"(addr));
}

__device__ __forceinline__ void cpa16(uint32_t* smem, const void* g) {
    uint32_t s = (uint32_t)__cvta_generic_to_shared(smem);
    asm volatile("cp.async.cg.shared.global [%0], [%1], 16;\n" :: "r"(s), "l"(g));
}
__device__ __forceinline__ void cp_commit() {
    asm volatile("cp.async.commit_group;\n");
}
template<int N>
__device__ __forceinline__ void cp_wait() {
    asm volatile("cp.async.wait_group %0;\n" :: "n"(N));
}

// ----------------------------------------------------------------------------
// Weight split + transpose: W[K][N] fp32 -> [N][K] bf16 hi/lo (remap supported)
// ----------------------------------------------------------------------------
__global__ void wsplit_t_kernel(const float* __restrict__ W,
                                __nv_bfloat16* __restrict__ th,
                                __nv_bfloat16* __restrict__ tl,
                                int K, int Nsrc, int coff, int rmul, int roff)
{
    __shared__ float tile[32][33];
    const int n0 = blockIdx.x * 32, k0 = blockIdx.y * 32;
    const int tx = threadIdx.x, ty = threadIdx.y;
#pragma unroll
    for (int r = ty; r < 32; r += 8)
        tile[r][tx] = W[(size_t)(k0 + r) * Nsrc + coff + n0 + tx];
    __syncthreads();
#pragma unroll
    for (int r = ty; r < 32; r += 8) {
        float v = tile[tx][r];
        __nv_bfloat16 hi, lo; split_bf16(v, hi, lo);
        size_t row = (size_t)rmul * (n0 + r) + roff;
        size_t idx = row * K + k0 + tx;
        th[idx] = hi;
        tl[idx] = lo;
    }
}

// Weight transpose to SINGLE fp16 with remap: W[K][N] fp32 -> [N'][K] half
__global__ void wsplit_t_fp16_kernel(const float* __restrict__ W,
                                     __half* __restrict__ th,
                                     int K, int Nsrc, int coff, int rmul, int roff)
{
    __shared__ float tile[32][33];
    const int n0 = blockIdx.x * 32, k0 = blockIdx.y * 32;
    const int tx = threadIdx.x, ty = threadIdx.y;
#pragma unroll
    for (int r = ty; r < 32; r += 8)
        tile[r][tx] = W[(size_t)(k0 + r) * Nsrc + coff + n0 + tx];
    __syncthreads();
#pragma unroll
    for (int r = ty; r < 32; r += 8) {
        size_t row = (size_t)rmul * (n0 + r) + roff;
        th[row * K + k0 + tx] = __float2half_rn(tile[tx][r]);
    }
}

// ----------------------------------------------------------------------------
// bf16 2-split 3-MMA GEMM (qkv / o-proj). CTA 64x128, 4 warps, 2 CTAs/SM.
// MODE 0: C = A@B   MODE 1: C = A@B + R
// ----------------------------------------------------------------------------
constexpr int ST_U32  = 12288;              // 48KB per stage (u32 units)
constexpr int TG_SMEM = 2 * ST_U32 * 4;     // 96KB

template<int MODE>
__global__ __launch_bounds__(128, 2)
void tg_kernel(const __nv_bfloat16* __restrict__ Ah, const __nv_bfloat16* __restrict__ Al,
               const __nv_bfloat16* __restrict__ Bh, const __nv_bfloat16* __restrict__ Bl,
               const float* __restrict__ R, float* __restrict__ C,
               int M, int N, int K)
{
    extern __shared__ uint32_t sm[];
    const uint32_t smem_b = (uint32_t)__cvta_generic_to_shared(sm);

    const int tid   = threadIdx.x;
    const int lane  = tid & 31;
    const int warpN = tid >> 5;
    const int g     = lane >> 2;
    const int tg    = lane & 3;
    const int rr    = lane & 7;
    const int ts    = lane >> 3;
    const int bx = blockIdx.x, by = blockIdx.y;

    float acc[4][4][4];
#pragma unroll
    for (int a = 0; a < 4; a++)
#pragma unroll
        for (int b = 0; b < 4; b++)
#pragma unroll
            for (int c = 0; c < 4; c++) acc[a][b][c] = 0.f;

    const int nk = K >> 6;

    auto fill = [&](int kt) {
        uint32_t* base = sm + (kt & 1) * ST_U32;
        const int k0 = kt * 64;
#pragma unroll
        for (int p = 0; p < 4; p++) {
            int i = tid + p * 128;
            int r = i >> 3, c = i & 7;
            int so = r * 32 + ((c ^ (r & 7)) << 2);
            size_t go = (size_t)(by * 64 + r) * K + k0 + c * 8;
            cpa16(base        + so, Ah + go);
            cpa16(base + 2048 + so, Al + go);
        }
#pragma unroll
        for (int p = 0; p < 8; p++) {
            int i = tid + p * 128;
            int r = i >> 3, c = i & 7;
            int so = r * 32 + ((c ^ (r & 7)) << 2);
            size_t go = (size_t)(bx * 128 + r) * K + k0 + c * 8;
            cpa16(base + 4096 + so, Bh + go);
            cpa16(base + 8192 + so, Bl + go);
        }
        cp_commit();
    };

    int mRow[4], nRow[2];
#pragma unroll
    for (int mt = 0; mt < 4; mt++) mRow[mt] = mt * 16 + ((ts & 1) << 3) + rr;
#pragma unroll
    for (int h = 0; h < 2; h++)    nRow[h]  = warpN * 32 + h * 16 + ((ts >> 1) << 3) + rr;
    const int khA = ts >> 1;
    const int khB = ts & 1;

    fill(0);

    for (int kt = 0; kt < nk; kt++) {
        if (kt + 1 < nk) {
            fill(kt + 1);
            cp_wait<1>();
        } else {
            cp_wait<0>();
        }
        __syncthreads();

        const uint32_t stb = smem_b + (uint32_t)(kt & 1) * 49152u;

#pragma unroll
        for (int ks = 0; ks < 4; ks++) {
            uint32_t aFh[4][4], aFl[4][4], bFh[4][2], bFl[4][2];
            const int ca = 2 * ks + khA;
            const int cb = 2 * ks + khB;
#pragma unroll
            for (int mt = 0; mt < 4; mt++) {
                int m = mRow[mt];
                uint32_t off = (uint32_t)(m * 128 + ((ca ^ (m & 7)) << 4));
                ldsm4(aFh[mt][0], aFh[mt][1], aFh[mt][2], aFh[mt][3], stb + off);
                ldsm4(aFl[mt][0], aFl[mt][1], aFl[mt][2], aFl[mt][3], stb + 8192u + off);
            }
#pragma unroll
            for (int h = 0; h < 2; h++) {
                int n = nRow[h];
                uint32_t off = (uint32_t)(n * 128 + ((cb ^ (n & 7)) << 4));
                ldsm4(bFh[2*h][0], bFh[2*h][1], bFh[2*h+1][0], bFh[2*h+1][1],
                      stb + 16384u + off);
                ldsm4(bFl[2*h][0], bFl[2*h][1], bFl[2*h+1][0], bFl[2*h+1][1],
                      stb + 32768u + off);
            }
#pragma unroll
            for (int mt = 0; mt < 4; mt++)
#pragma unroll
                for (int nt = 0; nt < 4; nt++) {
                    mma_bf16(acc[mt][nt], aFh[mt][0], aFh[mt][1], aFh[mt][2], aFh[mt][3],
                             bFh[nt][0], bFh[nt][1]);
                    mma_bf16(acc[mt][nt], aFh[mt][0], aFh[mt][1], aFh[mt][2], aFh[mt][3],
                             bFl[nt][0], bFl[nt][1]);
                    mma_bf16(acc[mt][nt], aFl[mt][0], aFl[mt][1], aFl[mt][2], aFl[mt][3],
                             bFh[nt][0], bFh[nt][1]);
                }
        }
        __syncthreads();
    }

    const size_t rowBase = (size_t)by * 64;
    const int    colBase = bx * 128 + warpN * 32;
#pragma unroll
    for (int mt = 0; mt < 4; mt++) {
        size_t r0 = rowBase + mt * 16 + g;
        size_t r1 = r0 + 8;
#pragma unroll
        for (int nt = 0; nt < 4; nt++) {
            int n = colBase + nt * 8 + 2 * tg;
            size_t i0 = r0 * N + n;
            size_t i1 = r1 * N + n;
            float2 v0 = make_float2(acc[mt][nt][0], acc[mt][nt][1]);
            float2 v1 = make_float2(acc[mt][nt][2], acc[mt][nt][3]);
            if (MODE == 1) {
                float2 q0 = *(const float2*)(R + i0);
                float2 q1 = *(const float2*)(R + i1);
                v0.x += q0.x; v0.y += q0.y;
                v1.x += q1.x; v1.y += q1.y;
            }
            *(float2*)(C + i0) = v0;
            *(float2*)(C + i1) = v1;
        }
    }
}

// ----------------------------------------------------------------------------
// fp16 GEMM (validated R12 config): C = A @ B. B single fp16.
// ASPLIT=2: A = hi+lo (2 MMA, exact A); ASPLIT=1: A single fp16 (1 MMA).
// CTA 64x128, 4 warps, 2-stage, 64KB smem, 2 CTAs/SM.
// MODE 0: C          MODE 1: C + R
// MODE 2: gate/up interleaved B -> silu(g)*u as SINGLE fp16 (row stride I_).
// MFAST: 1 -> mb=blockIdx.x (M fastest; lm_head DRAM streaming).
// ----------------------------------------------------------------------------
constexpr int STF_U32  = 8192;              // 32KB per stage (u32 units)
constexpr int TGF_SMEM = 2 * STF_U32 * 4;   // 64KB

template<int MODE, int MFAST, int ASPLIT>
__global__ __launch_bounds__(128, 2)
void tgf_kernel(const __half* __restrict__ Ah, const __half* __restrict__ Al,
                const __half* __restrict__ Bf,
                const float* __restrict__ R, float* __restrict__ C,
                __half* __restrict__ oh,
                int M, int N, int K)
{
    extern __shared__ uint32_t sm[];
    const uint32_t smem_b = (uint32_t)__cvta_generic_to_shared(sm);

    const int tid   = threadIdx.x;
    const int lane  = tid & 31;
    const int warpN = tid >> 5;
    const int g     = lane >> 2;
    const int tg    = lane & 3;
    const int rr    = lane & 7;
    const int ts    = lane >> 3;
    const int mb = MFAST ? blockIdx.x : blockIdx.y;
    const int nb = MFAST ? blockIdx.y : blockIdx.x;

    float acc[4][4][4];
#pragma unroll
    for (int a = 0; a < 4; a++)
#pragma unroll
        for (int b = 0; b < 4; b++)
#pragma unroll
            for (int c = 0; c < 4; c++) acc[a][b][c] = 0.f;

    const int nk = K >> 6;

    // per stage (u32): AsH[2048] AsL[2048] Bs[4096]
    auto fill = [&](int kt) {
        uint32_t* base = sm + (kt & 1) * STF_U32;
        const int k0 = kt * 64;
#pragma unroll
        for (int p = 0; p < 4; p++) {
            int i = tid + p * 128;
            int r = i >> 3, c = i & 7;
            int so = r * 32 + ((c ^ (r & 7)) << 2);
            size_t go = (size_t)(mb * 64 + r) * K + k0 + c * 8;
            cpa16(base + so, Ah + go);
            if (ASPLIT == 2) cpa16(base + 2048 + so, Al + go);
        }
#pragma unroll
        for (int p = 0; p < 8; p++) {
            int i = tid + p * 128;
            int r = i >> 3, c = i & 7;
            int so = r * 32 + ((c ^ (r & 7)) << 2);
            size_t go = (size_t)(nb * 128 + r) * K + k0 + c * 8;
            cpa16(base + 4096 + so, Bf + go);
        }
        cp_commit();
    };

    int mRow[4], nRow[2];
#pragma unroll
    for (int mt = 0; mt < 4; mt++) mRow[mt] = mt * 16 + ((ts & 1) << 3) + rr;
#pragma unroll
    for (int h = 0; h < 2; h++)    nRow[h]  = warpN * 32 + h * 16 + ((ts >> 1) << 3) + rr;
    const int khA = ts >> 1;
    const int khB = ts & 1;

    fill(0);

    for (int kt = 0; kt < nk; kt++) {
        if (kt + 1 < nk) {
            fill(kt + 1);
            cp_wait<1>();
        } else {
            cp_wait<0>();
        }
        __syncthreads();

        const uint32_t stb = smem_b + (uint32_t)(kt & 1) * 32768u;

#pragma unroll
        for (int ks = 0; ks < 4; ks++) {
            uint32_t aFh[4][4], aFl[4][4], bF[4][2];
            const int ca = 2 * ks + khA;
            const int cb = 2 * ks + khB;
#pragma unroll
            for (int mt = 0; mt < 4; mt++) {
                int m = mRow[mt];
                uint32_t off = (uint32_t)(m * 128 + ((ca ^ (m & 7)) << 4));
                ldsm4(aFh[mt][0], aFh[mt][1], aFh[mt][2], aFh[mt][3], stb + off);
                if (ASPLIT == 2)
                    ldsm4(aFl[mt][0], aFl[mt][1], aFl[mt][2], aFl[mt][3], stb + 8192u + off);
            }
#pragma unroll
            for (int h = 0; h < 2; h++) {
                int n = nRow[h];
                uint32_t off = (uint32_t)(n * 128 + ((cb ^ (n & 7)) << 4));
                ldsm4(bF[2*h][0], bF[2*h][1], bF[2*h+1][0], bF[2*h+1][1],
                      stb + 16384u + off);
            }
#pragma unroll
            for (int mt = 0; mt < 4; mt++)
#pragma unroll
                for (int nt = 0; nt < 4; nt++) {
                    mma_fp16(acc[mt][nt], aFh[mt][0], aFh[mt][1], aFh[mt][2], aFh[mt][3],
                             bF[nt][0], bF[nt][1]);
                    if (ASPLIT == 2)
                        mma_fp16(acc[mt][nt], aFl[mt][0], aFl[mt][1], aFl[mt][2], aFl[mt][3],
                                 bF[nt][0], bF[nt][1]);
                }
        }
        __syncthreads();
    }

    // ---- epilogue ----
    const size_t rowBase = (size_t)mb * 64;
    const int    colBase = nb * 128 + warpN * 32;
#pragma unroll
    for (int mt = 0; mt < 4; mt++) {
        size_t r0 = rowBase + mt * 16 + g;
        size_t r1 = r0 + 8;
#pragma unroll
        for (int nt = 0; nt < 4; nt++) {
            int n = colBase + nt * 8 + 2 * tg;
            if (MODE == 2) {
                size_t j = (size_t)(n >> 1);     // (gate, up) pair -> col j
                float g0 = acc[mt][nt][0], u0 = acc[mt][nt][1];
                float g1 = acc[mt][nt][2], u1 = acc[mt][nt][3];
                float v0 = g0 / (1.f + __expf(-g0)) * u0;
                float v1 = g1 / (1.f + __expf(-g1)) * u1;
                oh[r0 * I_ + j] = __float2half_rn(v0);   // single fp16 (one rounding event)
                oh[r1 * I_ + j] = __float2half_rn(v1);
            } else {
                size_t i0 = r0 * N + n;
                size_t i1 = r1 * N + n;
                float2 v0 = make_float2(acc[mt][nt][0], acc[mt][nt][1]);
                float2 v1 = make_float2(acc[mt][nt][2], acc[mt][nt][3]);
                if (MODE == 1) {
                    float2 q0 = *(const float2*)(R + i0);
                    float2 q1 = *(const float2*)(R + i1);
                    v0.x += q0.x; v0.y += q0.y;
                    v1.x += q1.x; v1.y += q1.y;
                }
                *(float2*)(C + i0) = v0;
                *(float2*)(C + i1) = v1;
            }
        }
    }
}

// ----------------------------------------------------------------------------
// Embedding gather
// ----------------------------------------------------------------------------
__global__ void embed_kernel(const int* __restrict__ ids,
                             const float* __restrict__ emb,
                             float* __restrict__ h)
{
    int t = blockIdx.x;
    int id = ids[t];
    const float4* src = (const float4*)(emb + (size_t)id * H_);
    float4* dst = (float4*)(h + (size_t)t * H_);
    for (int i = threadIdx.x; i < H_ / 4; i += blockDim.x) dst[i] = src[i];
}

// ----------------------------------------------------------------------------
// RMSNorm -> bf16 (hi, lo)
// ----------------------------------------------------------------------------
__global__ void rmsnorm_kernel(const float* __restrict__ h,
                               const float* __restrict__ w,
                               __nv_bfloat16* __restrict__ xh,
                               __nv_bfloat16* __restrict__ xl)
{
    int t = blockIdx.x;
    const float* hr = h + (size_t)t * H_;
    __shared__ float red[256];
    float s = 0.f;
    for (int i = threadIdx.x; i < H_; i += 256) { float v = hr[i]; s += v * v; }
    red[threadIdx.x] = s; __syncthreads();
    for (int st = 128; st > 0; st >>= 1) {
        if (threadIdx.x < st) red[threadIdx.x] += red[threadIdx.x + st];
        __syncthreads();
    }
    float scale = rsqrtf(red[0] / (float)H_ + 1e-5f);
    for (int i = threadIdx.x; i < H_; i += 256) {
        float v = hr[i] * scale * w[i];
        __nv_bfloat16 hi, lo; split_bf16(v, hi, lo);
        xh[(size_t)t * H_ + i] = hi;
        xl[(size_t)t * H_ + i] = lo;
    }
}

// RMSNorm -> fp16 (hi, lo)
__global__ void rmsnorm_fp16_kernel(const float* __restrict__ h,
                                    const float* __restrict__ w,
                                    __half* __restrict__ xh,
                                    __half* __restrict__ xl)
{
    int t = blockIdx.x;
    const float* hr = h + (size_t)t * H_;
    __shared__ float red[256];
    float s = 0.f;
    for (int i = threadIdx.x; i < H_; i += 256) { float v = hr[i]; s += v * v; }
    red[threadIdx.x] = s; __syncthreads();
    for (int st = 128; st > 0; st >>= 1) {
        if (threadIdx.x < st) red[threadIdx.x] += red[threadIdx.x + st];
        __syncthreads();
    }
    float scale = rsqrtf(red[0] / (float)H_ + 1e-5f);
    for (int i = threadIdx.x; i < H_; i += 256) {
        float v = hr[i] * scale * w[i];
        __half hi, lo; split_fp16(v, hi, lo);
        xh[(size_t)t * H_ + i] = hi;
        xl[(size_t)t * H_ + i] = lo;
    }
}

// ----------------------------------------------------------------------------
// Q/K prep: fused RoPE + Q-scale + bf16 hi/lo split
// ----------------------------------------------------------------------------
__global__ void qkprep_kernel(const float* __restrict__ qkv, const int* __restrict__ pos,
                              __nv_bfloat16* __restrict__ Qh, __nv_bfloat16* __restrict__ Ql,
                              __nv_bfloat16* __restrict__ Kh, __nv_bfloat16* __restrict__ Kl)
{
    int idx = blockIdx.x * blockDim.x + threadIdx.x;
    if (idx >= T_ * 24 * 64) return;
    int i    = idx & 63;
    int head = (idx >> 6) % 24;
    int t    = idx / (24 * 64);
    int b = t / S_, s = t % S_;

    float p = (float)pos[t];
    float e = ((float)i / 64.0f) * 13.28771237954945f;  // log2(10000)
    float inv = exp2f(-e);
    float ang = p * inv;
    float sn, cs;
    sincosf(ang, &sn, &cs);

    int off = (head < NH_) ? head * HD_ : KOFF_ + (head - NH_) * HD_;
    const float* v = qkv + (size_t)t * QKVN_ + off;
    float x1 = v[i], x2 = v[i + 64];
    float r1 = x1 * cs - x2 * sn;
    float r2 = x2 * cs + x1 * sn;

    __nv_bfloat16 *dh, *dl;
    if (head < NH_) {
        const float scale = 0.08838834764831845f;
        r1 *= scale; r2 *= scale;
        size_t base = (((size_t)(b * NH_ + head)) * S_ + s) * HD_;
        dh = Qh + base; dl = Ql + base;
    } else {
        size_t base = (((size_t)(b * NKV_ + head - NH_)) * S_ + s) * HD_;
        dh = Kh + base; dl = Kl + base;
    }
    __nv_bfloat16 h1, l1, h2, l2;
    split_bf16(r1, h1, l1);
    split_bf16(r2, h2, l2);
    dh[i] = h1;      dl[i] = l1;
    dh[i + 64] = h2; dl[i + 64] = l2;
}

// ----------------------------------------------------------------------------
// V prep: transpose to [B][NKV][HD][S] + bf16 hi/lo split
// ----------------------------------------------------------------------------
__global__ void vprep_kernel(const float* __restrict__ qkv,
                             __nv_bfloat16* __restrict__ Vth,
                             __nv_bfloat16* __restrict__ Vtl)
{
    __shared__ float tile[32][33];
    const int z = blockIdx.z;
    const int b = z / NKV_, hkv = z % NKV_;
    const int s0 = blockIdx.x * 32, d0 = blockIdx.y * 32;
    const int tx = threadIdx.x, ty = threadIdx.y;
#pragma unroll
    for (int r = ty; r < 32; r += 8)
        tile[r][tx] = qkv[(size_t)(b * S_ + s0 + r) * QKVN_ + VOFF_ + hkv * HD_ + d0 + tx];
    __syncthreads();
    size_t base = ((size_t)(b * NKV_ + hkv)) * HD_ * S_;
#pragma unroll
    for (int r = ty; r < 32; r += 8) {
        float v = tile[tx][r];
        __nv_bfloat16 hi, lo; split_bf16(v, hi, lo);
        size_t idx = base + (size_t)(d0 + r) * S_ + s0 + tx;
        Vth[idx] = hi;
        Vtl[idx] = lo;
    }
}

// ----------------------------------------------------------------------------
// Flash attention (validated R5 kernel, unchanged)
// ----------------------------------------------------------------------------
__global__ __launch_bounds__(128)
void flash_kernel(const __nv_bfloat16* __restrict__ Qh, const __nv_bfloat16* __restrict__ Ql,
                  const __nv_bfloat16* __restrict__ Kh, const __nv_bfloat16* __restrict__ Kl,
                  const __nv_bfloat16* __restrict__ Vth, const __nv_bfloat16* __restrict__ Vtl,
                  __nv_bfloat16* __restrict__ Oh, __nv_bfloat16* __restrict__ Ol)
{
    extern __shared__ uint32_t sm[];
    uint32_t* KsH = sm;
    uint32_t* KsL = sm + 4096;
    uint32_t* VsH = sm + 8192;
    uint32_t* VsL = sm + 12288;

    const int qt = (int)gridDim.x - 1 - (int)blockIdx.x;
    const int z  = blockIdx.y;
    const int b  = z >> 4, hq = z & 15, hkv = hq >> 1;

    const int tid  = threadIdx.x;
    const int lane = tid & 31;
    const int w    = tid >> 5;
    const int g    = lane >> 2;
    const int tg   = lane & 3;

    uint32_t qFh[8][4], qFl[8][4];
    {
        const uint32_t* qbh = (const uint32_t*)(Qh + (((size_t)(b * NH_ + hq)) * S_ + qt * 64 + w * 16) * HD_);
        const uint32_t* qbl = (const uint32_t*)(Ql + (((size_t)(b * NH_ + hq)) * S_ + qt * 64 + w * 16) * HD_);
#pragma unroll
        for (int ks = 0; ks < 8; ks++) {
            int c = 8 * ks + tg;
            qFh[ks][0] = qbh[g * 64 + c];
            qFh[ks][1] = qbh[(g + 8) * 64 + c];
            qFh[ks][2] = qbh[g * 64 + c + 4];
            qFh[ks][3] = qbh[(g + 8) * 64 + c + 4];
            qFl[ks][0] = qbl[g * 64 + c];
            qFl[ks][1] = qbl[(g + 8) * 64 + c];
            qFl[ks][2] = qbl[g * 64 + c + 4];
            qFl[ks][3] = qbl[(g + 8) * 64 + c + 4];
        }
    }

    float oAcc[16][4];
#pragma unroll
    for (int i = 0; i < 16; i++)
#pragma unroll
        for (int j = 0; j < 4; j++) oAcc[i][j] = 0.f;
    float mA = -1e30f, mB = -1e30f, lA = 0.f, lB = 0.f;

    const __nv_bfloat16* KgH = Kh  + ((size_t)(b * NKV_ + hkv)) * S_ * HD_;
    const __nv_bfloat16* KgL = Kl  + ((size_t)(b * NKV_ + hkv)) * S_ * HD_;
    const __nv_bfloat16* VgH = Vth + ((size_t)(b * NKV_ + hkv)) * HD_ * S_;
    const __nv_bfloat16* VgL = Vtl + ((size_t)(b * NKV_ + hkv)) * HD_ * S_;

    for (int kt = 0; kt <= qt; kt++) {
#pragma unroll
        for (int p = 0; p < 8; p++) {
            int i = tid + p * 128;
            int r = i >> 4, cc = i & 15;
            int dst = r * 64 + ((cc ^ (r & 7)) << 2);
            cpa16(KsH + dst, KgH + (size_t)(kt * 64 + r) * HD_ + cc * 8);
            cpa16(KsL + dst, KgL + (size_t)(kt * 64 + r) * HD_ + cc * 8);
        }
#pragma unroll
        for (int p = 0; p < 8; p++) {
            int i = tid + p * 128;
            int n = i >> 3, cc = i & 7;
            int dst = n * 32 + ((cc ^ (n & 7)) << 2);
            cpa16(VsH + dst, VgH + (size_t)n * S_ + kt * 64 + cc * 8);
            cpa16(VsL + dst, VgL + (size_t)n * S_ + kt * 64 + cc * 8);
        }
        cp_commit();
        cp_wait<0>();
        __syncthreads();

        float sAcc[8][4];
#pragma unroll
        for (int i = 0; i < 8; i++)
#pragma unroll
            for (int j = 0; j < 4; j++) sAcc[i][j] = 0.f;

#pragma unroll
        for (int ks = 0; ks < 8; ks++) {
            uint32_t kFh[8][2], kFl[8][2];
            const int c0 = 8 * ks + tg;
#pragma unroll
            for (int nt = 0; nt < 8; nt++) {
                int key = nt * 8 + g;
                int sw = (key & 7) << 2;
                int o0 = key * 64 + (c0 ^ sw);
                int o1 = key * 64 + ((c0 + 4) ^ sw);
                kFh[nt][0] = KsH[o0]; kFh[nt][1] = KsH[o1];
                kFl[nt][0] = KsL[o0]; kFl[nt][1] = KsL[o1];
            }
#pragma unroll
            for (int nt = 0; nt < 8; nt++) {
                mma_bf16(sAcc[nt], qFh[ks][0], qFh[ks][1], qFh[ks][2], qFh[ks][3],
                         kFh[nt][0], kFh[nt][1]);
                mma_bf16(sAcc[nt], qFh[ks][0], qFh[ks][1], qFh[ks][2], qFh[ks][3],
                         kFl[nt][0], kFl[nt][1]);
                mma_bf16(sAcc[nt], qFl[ks][0], qFl[ks][1], qFl[ks][2], qFl[ks][3],
                         kFh[nt][0], kFh[nt][1]);
            }
        }

        if (kt == qt) {
            const int qrA = w * 16 + g, qrB = qrA + 8;
#pragma unroll
            for (int nt = 0; nt < 8; nt++) {
                int k0 = nt * 8 + 2 * tg, k1 = k0 + 1;
                if (k0 > qrA) sAcc[nt][0] = -1e30f;
                if (k1 > qrA) sAcc[nt][1] = -1e30f;
                if (k0 > qrB) sAcc[nt][2] = -1e30f;
                if (k1 > qrB) sAcc[nt][3] = -1e30f;
            }
        }

        float tmA = -1e30f, tmB = -1e30f;
#pragma unroll
        for (int nt = 0; nt < 8; nt++) {
            tmA = fmaxf(tmA, fmaxf(sAcc[nt][0], sAcc[nt][1]));
            tmB = fmaxf(tmB, fmaxf(sAcc[nt][2], sAcc[nt][3]));
        }
        tmA = fmaxf(tmA, __shfl_xor_sync(0xffffffff, tmA, 1));
        tmA = fmaxf(tmA, __shfl_xor_sync(0xffffffff, tmA, 2));
        tmB = fmaxf(tmB, __shfl_xor_sync(0xffffffff, tmB, 1));
        tmB = fmaxf(tmB, __shfl_xor_sync(0xffffffff, tmB, 2));
        float nmA = fmaxf(mA, tmA), nmB = fmaxf(mB, tmB);
        float eA = __expf(mA - nmA), eB = __expf(mB - nmB);

        float rsA = 0.f, rsB = 0.f;
#pragma unroll
        for (int nt = 0; nt < 8; nt++) {
            sAcc[nt][0] = __expf(sAcc[nt][0] - nmA);
            sAcc[nt][1] = __expf(sAcc[nt][1] - nmA);
            sAcc[nt][2] = __expf(sAcc[nt][2] - nmB);
            sAcc[nt][3] = __expf(sAcc[nt][3] - nmB);
            rsA += sAcc[nt][0] + sAcc[nt][1];
            rsB += sAcc[nt][2] + sAcc[nt][3];
        }
        rsA += __shfl_xor_sync(0xffffffff, rsA, 1);
        rsA += __shfl_xor_sync(0xffffffff, rsA, 2);
        rsB += __shfl_xor_sync(0xffffffff, rsB, 1);
        rsB += __shfl_xor_sync(0xffffffff, rsB, 2);
        lA = lA * eA + rsA;
        lB = lB * eB + rsB;
        mA = nmA; mB = nmB;
#pragma unroll
        for (int nt = 0; nt < 16; nt++) {
            oAcc[nt][0] *= eA; oAcc[nt][1] *= eA;
            oAcc[nt][2] *= eB; oAcc[nt][3] *= eB;
        }

#pragma unroll
        for (int ks2 = 0; ks2 < 4; ks2++) {
            uint32_t ph[4], pl[4];
#pragma unroll
            for (int q = 0; q < 2; q++) {
                const float* s4 = sAcc[2 * ks2 + q];
                uint32_t hp0 = pack_bf16x2(s4[0], s4[1]);
                uint32_t hp1 = pack_bf16x2(s4[2], s4[3]);
                float h00 = __uint_as_float(hp0 << 16);
                float h01 = __uint_as_float(hp0 & 0xFFFF0000u);
                float h10 = __uint_as_float(hp1 << 16);
                float h11 = __uint_as_float(hp1 & 0xFFFF0000u);
                ph[2 * q]     = hp0;
                ph[2 * q + 1] = hp1;
                pl[2 * q]     = pack_bf16x2(s4[0] - h00, s4[1] - h01);
                pl[2 * q + 1] = pack_bf16x2(s4[2] - h10, s4[3] - h11);
            }
            const int kp = 8 * ks2 + tg;
#pragma unroll
            for (int nt2 = 0; nt2 < 16; nt2++) {
                int n = nt2 * 8 + g;
                int sw = (n & 7) << 2;
                int o0 = n * 32 + (kp ^ sw);
                int o1 = n * 32 + ((kp + 4) ^ sw);
                uint32_t v0h = VsH[o0], v1h = VsH[o1];
                uint32_t v0l = VsL[o0], v1l = VsL[o1];
                mma_bf16(oAcc[nt2], ph[0], ph[1], ph[2], ph[3], v0h, v1h);
                mma_bf16(oAcc[nt2], ph[0], ph[1], ph[2], ph[3], v0l, v1l);
                mma_bf16(oAcc[nt2], pl[0], pl[1], pl[2], pl[3], v0h, v1h);
            }
        }
        __syncthreads();
    }

    const float ilA = 1.f / lA, ilB = 1.f / lB;
    const size_t tA = (size_t)b * S_ + qt * 64 + w * 16 + g;
    const size_t tB = tA + 8;
#pragma unroll
    for (int nt2 = 0; nt2 < 16; nt2++) {
        int col = hq * HD_ + nt2 * 8 + 2 * tg;
        float a0 = oAcc[nt2][0] * ilA, a1 = oAcc[nt2][1] * ilA;
        float b0 = oAcc[nt2][2] * ilB, b1 = oAcc[nt2][3] * ilB;

        uint32_t ahp = pack_bf16x2(a0, a1);
        uint32_t bhp = pack_bf16x2(b0, b1);
        float ah0 = __uint_as_float(ahp << 16), ah1 = __uint_as_float(ahp & 0xFFFF0000u);
        float bh0 = __uint_as_float(bhp << 16), bh1 = __uint_as_float(bhp & 0xFFFF0000u);
        uint32_t alp = pack_bf16x2(a0 - ah0, a1 - ah1);
        uint32_t blp = pack_bf16x2(b0 - bh0, b1 - bh1);

        *(uint32_t*)(Oh + tA * H_ + col) = ahp;
        *(uint32_t*)(Ol + tA * H_ + col) = alp;
        *(uint32_t*)(Oh + tB * H_ + col) = bhp;
        *(uint32_t*)(Ol + tB * H_ + col) = blp;
    }
}

// ----------------------------------------------------------------------------
// Host orchestration
// ----------------------------------------------------------------------------
extern "C" void kernel_launch(void* const* d_in, const int* in_sizes, int n_in,
                              void* d_out, int out_size)
{
    (void)in_sizes; (void)n_in; (void)out_size;
    const int*   ids    = (const int*)  d_in[0];
    const int*   pos    = (const int*)  d_in[1];
    const float* emb    = (const float*)d_in[2];
    const float* Wqkv   = (const float*)d_in[3];
    const float* Wo     = (const float*)d_in[4];
    const float* Wgu    = (const float*)d_in[5];
    const float* Wdn    = (const float*)d_in[6];
    const float* ln1    = (const float*)d_in[7];
    const float* ln2    = (const float*)d_in[8];
    const float* normw  = (const float*)d_in[9];
    const float* lmhead = (const float*)d_in[10];
    float* out = (float*)d_out;

    cudaFuncSetAttribute(tg_kernel<0>, cudaFuncAttributeMaxDynamicSharedMemorySize, TG_SMEM);
    cudaFuncSetAttribute(tg_kernel<1>, cudaFuncAttributeMaxDynamicSharedMemorySize, TG_SMEM);
    cudaFuncSetAttribute((const void*)tgf_kernel<0,1,1>, cudaFuncAttributeMaxDynamicSharedMemorySize, TGF_SMEM);
    cudaFuncSetAttribute((const void*)tgf_kernel<1,0,1>, cudaFuncAttributeMaxDynamicSharedMemorySize, TGF_SMEM);
    cudaFuncSetAttribute((const void*)tgf_kernel<2,0,2>, cudaFuncAttributeMaxDynamicSharedMemorySize, TGF_SMEM);
    cudaFuncSetAttribute(flash_kernel, cudaFuncAttributeMaxDynamicSharedMemorySize, 65536);

    float *h, *qkv;
    __nv_bfloat16 *x, *xl, *attn, *attnl, *si, *wh, *wl;
    __nv_bfloat16 *qh, *ql, *kh, *kl, *vth, *vtl;
    cudaGetSymbolAddress((void**)&h,     g_h);
    cudaGetSymbolAddress((void**)&x,     g_x);
    cudaGetSymbolAddress((void**)&xl,    g_xl);
    cudaGetSymbolAddress((void**)&qkv,   g_qkv);
    cudaGetSymbolAddress((void**)&attn,  g_attn);
    cudaGetSymbolAddress((void**)&attnl, g_attnl);
    cudaGetSymbolAddress((void**)&si,    g_si);
    cudaGetSymbolAddress((void**)&wh,    g_wh);
    cudaGetSymbolAddress((void**)&wl,    g_wl);
    cudaGetSymbolAddress((void**)&qh,    g_qh);
    cudaGetSymbolAddress((void**)&ql,    g_ql);
    cudaGetSymbolAddress((void**)&kh,    g_kh);
    cudaGetSymbolAddress((void**)&kl,    g_kl);
    cudaGetSymbolAddress((void**)&vth,   g_vth);
    cudaGetSymbolAddress((void**)&vtl,   g_vtl);

    embed_kernel<<<T_, 256>>>(ids, emb, h);

    for (int l = 0; l < L_; l++) {
        const float* wqkv = Wqkv + (size_t)l * H_ * QKVN_;
        const float* wo   = Wo   + (size_t)l * H_ * H_;
        const float* wgu  = Wgu  + (size_t)l * H_ * (2 * I_);
        const float* wdn  = Wdn  + (size_t)l * I_ * H_;

        // ---- attention block (bf16 3-MMA, validated) ----
        rmsnorm_kernel<<<T_, 256>>>(h, ln1 + (size_t)l * H_, x, xl);
        wsplit_t_kernel<<<dim3(QKVN_ / 32, H_ / 32), dim3(32, 8)>>>(wqkv, wh, wl, H_, QKVN_, 0, 1, 0);
        tg_kernel<0><<<dim3(QKVN_ / 128, T_ / 64), 128, TG_SMEM>>>(x, xl, wh, wl, nullptr, qkv,
                                                                   T_, QKVN_, H_);

        {
            int tot = T_ * 24 * 64;
            qkprep_kernel<<<(tot + 255) / 256, 256>>>(qkv, pos, qh, ql, kh, kl);
        }
        vprep_kernel<<<dim3(S_ / 32, HD_ / 32, B_ * NKV_), dim3(32, 8)>>>(qkv, vth, vtl);

        flash_kernel<<<dim3(S_ / 64, B_ * NH_), 128, 65536>>>(qh, ql, kh, kl, vth, vtl,
                                                              attn, attnl);

        wsplit_t_kernel<<<dim3(H_ / 32, H_ / 32), dim3(32, 8)>>>(wo, wh, wl, H_, H_, 0, 1, 0);
        tg_kernel<1><<<dim3(H_ / 128, T_ / 64), 128, TG_SMEM>>>(attn, attnl, wh, wl, h, h,
                                                                T_, H_, H_);

        // ---- MLP block (fp16; gate-up exact-A 2-MMA, down-proj single-A 1-MMA) ----
        rmsnorm_fp16_kernel<<<T_, 256>>>(h, ln2 + (size_t)l * H_, (__half*)x, (__half*)xl);
        wsplit_t_fp16_kernel<<<dim3(I_ / 32, H_ / 32), dim3(32, 8)>>>(wgu, (__half*)wh,
                                                                      H_, 2 * I_, 0, 2, 0);
        wsplit_t_fp16_kernel<<<dim3(I_ / 32, H_ / 32), dim3(32, 8)>>>(wgu, (__half*)wh,
                                                                      H_, 2 * I_, I_, 2, 1);
        tgf_kernel<2, 0, 2><<<dim3(2 * I_ / 128, T_ / 64), 128, TGF_SMEM>>>(
            (const __half*)x, (const __half*)xl, (const __half*)wh,
            nullptr, nullptr, (__half*)si, T_, 2 * I_, H_);

        wsplit_t_fp16_kernel<<<dim3(H_ / 32, I_ / 32), dim3(32, 8)>>>(wdn, (__half*)wh,
                                                                      I_, H_, 0, 1, 0);
        tgf_kernel<1, 0, 1><<<dim3(H_ / 128, T_ / 64), 128, TGF_SMEM>>>(
            (const __half*)si, nullptr, (const __half*)wh,
            h, h, nullptr, T_, H_, I_);
    }

    // ---- final norm + fully-fp16 1-MMA lm_head (M-fastest: stream 128MB B once) ----
    rmsnorm_fp16_kernel<<<T_, 256>>>(h, normw, (__half*)x, (__half*)xl);
    wsplit_t_fp16_kernel<<<dim3(VOCAB_ / 32, H_ / 32), dim3(32, 8)>>>(lmhead, (__half*)wh,
                                                                      H_, VOCAB_, 0, 1, 0);
    tgf_kernel<0, 1, 1><<<dim3(T_ / 64, VOCAB_ / 128), 128, TGF_SMEM>>>(
        (const __half*)x, (const __half*)xl, (const __half*)wh,
        nullptr, out, nullptr, T_, VOCAB_, H_);
}

// round 16
// speedup vs baseline: 1.3364x; 1.1360x over previous
#include <cuda_runtime.h>
#include <cuda_bf16.h>
#include <cuda_fp16.h>
#include <math.h>
#include <stdint.h>

// ----------------------------------------------------------------------------
// Model constants
// ----------------------------------------------------------------------------
constexpr int B_    = 2;
constexpr int S_    = 2048;
constexpr int T_    = B_ * S_;        // 4096 tokens
constexpr int H_    = 2048;
constexpr int NH_   = 16;
constexpr int NKV_  = 8;
constexpr int HD_   = 128;
constexpr int I_    = 5632;
constexpr int L_    = 2;
constexpr int VOCAB_= 32000;
constexpr int QKVN_ = (NH_ + 2 * NKV_) * HD_;  // 4096
constexpr int KOFF_ = NH_ * HD_;               // 2048
constexpr int VOFF_ = KOFF_ + NKV_ * HD_;      // 3072

// ----------------------------------------------------------------------------
// Scratch (device globals: allocation-free rule)
// ----------------------------------------------------------------------------
__device__ float          g_h    [(size_t)T_ * H_];
__device__ __nv_bfloat16  g_x    [(size_t)T_ * H_];
__device__ __nv_bfloat16  g_xl   [(size_t)T_ * H_];
__device__ float          g_qkv  [(size_t)T_ * QKVN_];
__device__ __nv_bfloat16  g_attn [(size_t)T_ * H_];
__device__ __nv_bfloat16  g_attnl[(size_t)T_ * H_];
__device__ __nv_bfloat16  g_si   [(size_t)T_ * I_];
__device__ __nv_bfloat16  g_wh   [(size_t)H_ * VOCAB_];  // weight staging (hi / fp16)
__device__ __nv_bfloat16  g_wl   [(size_t)H_ * VOCAB_];  // lo
// flash-attention operands
__device__ __nv_bfloat16  g_qh [(size_t)B_ * NH_  * S_ * HD_];
__device__ __nv_bfloat16  g_ql [(size_t)B_ * NH_  * S_ * HD_];
__device__ __nv_bfloat16  g_kh [(size_t)B_ * NKV_ * S_ * HD_];
__device__ __nv_bfloat16  g_kl [(size_t)B_ * NKV_ * S_ * HD_];
__device__ __nv_bfloat16  g_vth[(size_t)B_ * NKV_ * HD_ * S_];
__device__ __nv_bfloat16  g_vtl[(size_t)B_ * NKV_ * HD_ * S_];

// ----------------------------------------------------------------------------
// helpers
// ----------------------------------------------------------------------------
__device__ __forceinline__ void split_bf16(float v, __nv_bfloat16& hi, __nv_bfloat16& lo) {
    hi = __float2bfloat16(v);
    lo = __float2bfloat16(v - __bfloat162float(hi));
}

__device__ __forceinline__ void split_fp16(float v, __half& hi, __half& lo) {
    hi = __float2half_rn(v);
    lo = __float2half_rn(v - __half2float(hi));
}

__device__ __forceinline__ uint32_t pack_bf16x2(float x, float y) {
    __nv_bfloat162 t = __float22bfloat162_rn(make_float2(x, y));
    uint32_t u; memcpy(&u, &t, 4);
    return u;
}

__device__ __forceinline__ void mma_bf16(float c[4],
                                         uint32_t a0, uint32_t a1, uint32_t a2, uint32_t a3,
                                         uint32_t b0, uint32_t b1)
{
    asm volatile(
        "mma.sync.aligned.m16n8k16.row.col.f32.bf16.bf16.f32 "
        "{%0,%1,%2,%3}, {%4,%5,%6,%7}, {%8,%9}, {%0,%1,%2,%3};\n"
        : "+f"(c[0]), "+f"(c[1]), "+f"(c[2]), "+f"(c[3])
        : "r"(a0), "r"(a1), "r"(a2), "r"(a3), "r"(b0), "r"(b1));
}

__device__ __forceinline__ void mma_fp16(float c[4],
                                         uint32_t a0, uint32_t a1, uint32_t a2, uint32_t a3,
                                         uint32_t b0, uint32_t b1)
{
    asm volatile(
        "mma.sync.aligned.m16n8k16.row.col.f32.f16.f16.f32 "
        "{%0,%1,%2,%3}, {%4,%5,%6,%7}, {%8,%9}, {%0,%1,%2,%3};\n"
        : "+f"(c[0]), "+f"(c[1]), "+f"(c[2]), "+f"(c[3])
        : "r"(a0), "r"(a1), "r"(a2), "r"(a3), "r"(b0), "r"(b1));
}

__device__ __forceinline__ void ldsm4(uint32_t& r0, uint32_t& r1, uint32_t& r2, uint32_t& r3,
                                      uint32_t addr)
{
    asm volatile("ldmatrix.sync.aligned.m8n8.x4.shared.b16 {%0,%1,%2,%3}, [%4];"
                 : "=r"(r0), "=r"(r1), "=r"(r2), "=r"(r3) : "r"(addr));
}

__device__ __forceinline__ void cpa16(uint32_t* smem, const void* g) {
    uint32_t s = (uint32_t)__cvta_generic_to_shared(smem);
    asm volatile("cp.async.cg.shared.global [%0], [%1], 16;\n" :: "r"(s), "l"(g));
}
__device__ __forceinline__ void cp_commit() {
    asm volatile("cp.async.commit_group;\n");
}
template<int N>
__device__ __forceinline__ void cp_wait() {
    asm volatile("cp.async.wait_group %0;\n" :: "n"(N));
}

// ----------------------------------------------------------------------------
// Weight split + transpose: W[K][N] fp32 -> [N][K] bf16 hi/lo (remap supported)
// ----------------------------------------------------------------------------
__global__ void wsplit_t_kernel(const float* __restrict__ W,
                                __nv_bfloat16* __restrict__ th,
                                __nv_bfloat16* __restrict__ tl,
                                int K, int Nsrc, int coff, int rmul, int roff)
{
    __shared__ float tile[32][33];
    const int n0 = blockIdx.x * 32, k0 = blockIdx.y * 32;
    const int tx = threadIdx.x, ty = threadIdx.y;
#pragma unroll
    for (int r = ty; r < 32; r += 8)
        tile[r][tx] = W[(size_t)(k0 + r) * Nsrc + coff + n0 + tx];
    __syncthreads();
#pragma unroll
    for (int r = ty; r < 32; r += 8) {
        float v = tile[tx][r];
        __nv_bfloat16 hi, lo; split_bf16(v, hi, lo);
        size_t row = (size_t)rmul * (n0 + r) + roff;
        size_t idx = row * K + k0 + tx;
        th[idx] = hi;
        tl[idx] = lo;
    }
}

// Weight transpose to SINGLE fp16 with remap: W[K][N] fp32 -> [N'][K] half
__global__ void wsplit_t_fp16_kernel(const float* __restrict__ W,
                                     __half* __restrict__ th,
                                     int K, int Nsrc, int coff, int rmul, int roff)
{
    __shared__ float tile[32][33];
    const int n0 = blockIdx.x * 32, k0 = blockIdx.y * 32;
    const int tx = threadIdx.x, ty = threadIdx.y;
#pragma unroll
    for (int r = ty; r < 32; r += 8)
        tile[r][tx] = W[(size_t)(k0 + r) * Nsrc + coff + n0 + tx];
    __syncthreads();
#pragma unroll
    for (int r = ty; r < 32; r += 8) {
        size_t row = (size_t)rmul * (n0 + r) + roff;
        th[row * K + k0 + tx] = __float2half_rn(tile[tx][r]);
    }
}

// ----------------------------------------------------------------------------
// bf16 2-split 3-MMA GEMM (qkv / o-proj). CTA 64x128, 4 warps, 2 CTAs/SM.
// MODE 0: C = A@B   MODE 1: C = A@B + R
// ----------------------------------------------------------------------------
constexpr int ST_U32  = 12288;              // 48KB per stage (u32 units)
constexpr int TG_SMEM = 2 * ST_U32 * 4;     // 96KB

template<int MODE>
__global__ __launch_bounds__(128, 2)
void tg_kernel(const __nv_bfloat16* __restrict__ Ah, const __nv_bfloat16* __restrict__ Al,
               const __nv_bfloat16* __restrict__ Bh, const __nv_bfloat16* __restrict__ Bl,
               const float* __restrict__ R, float* __restrict__ C,
               int M, int N, int K)
{
    extern __shared__ uint32_t sm[];
    const uint32_t smem_b = (uint32_t)__cvta_generic_to_shared(sm);

    const int tid   = threadIdx.x;
    const int lane  = tid & 31;
    const int warpN = tid >> 5;
    const int g     = lane >> 2;
    const int tg    = lane & 3;
    const int rr    = lane & 7;
    const int ts    = lane >> 3;
    const int bx = blockIdx.x, by = blockIdx.y;

    float acc[4][4][4];
#pragma unroll
    for (int a = 0; a < 4; a++)
#pragma unroll
        for (int b = 0; b < 4; b++)
#pragma unroll
            for (int c = 0; c < 4; c++) acc[a][b][c] = 0.f;

    const int nk = K >> 6;

    auto fill = [&](int kt) {
        uint32_t* base = sm + (kt & 1) * ST_U32;
        const int k0 = kt * 64;
#pragma unroll
        for (int p = 0; p < 4; p++) {
            int i = tid + p * 128;
            int r = i >> 3, c = i & 7;
            int so = r * 32 + ((c ^ (r & 7)) << 2);
            size_t go = (size_t)(by * 64 + r) * K + k0 + c * 8;
            cpa16(base        + so, Ah + go);
            cpa16(base + 2048 + so, Al + go);
        }
#pragma unroll
        for (int p = 0; p < 8; p++) {
            int i = tid + p * 128;
            int r = i >> 3, c = i & 7;
            int so = r * 32 + ((c ^ (r & 7)) << 2);
            size_t go = (size_t)(bx * 128 + r) * K + k0 + c * 8;
            cpa16(base + 4096 + so, Bh + go);
            cpa16(base + 8192 + so, Bl + go);
        }
        cp_commit();
    };

    int mRow[4], nRow[2];
#pragma unroll
    for (int mt = 0; mt < 4; mt++) mRow[mt] = mt * 16 + ((ts & 1) << 3) + rr;
#pragma unroll
    for (int h = 0; h < 2; h++)    nRow[h]  = warpN * 32 + h * 16 + ((ts >> 1) << 3) + rr;
    const int khA = ts >> 1;
    const int khB = ts & 1;

    fill(0);

    for (int kt = 0; kt < nk; kt++) {
        if (kt + 1 < nk) {
            fill(kt + 1);
            cp_wait<1>();
        } else {
            cp_wait<0>();
        }
        __syncthreads();

        const uint32_t stb = smem_b + (uint32_t)(kt & 1) * 49152u;

#pragma unroll
        for (int ks = 0; ks < 4; ks++) {
            uint32_t aFh[4][4], aFl[4][4], bFh[4][2], bFl[4][2];
            const int ca = 2 * ks + khA;
            const int cb = 2 * ks + khB;
#pragma unroll
            for (int mt = 0; mt < 4; mt++) {
                int m = mRow[mt];
                uint32_t off = (uint32_t)(m * 128 + ((ca ^ (m & 7)) << 4));
                ldsm4(aFh[mt][0], aFh[mt][1], aFh[mt][2], aFh[mt][3], stb + off);
                ldsm4(aFl[mt][0], aFl[mt][1], aFl[mt][2], aFl[mt][3], stb + 8192u + off);
            }
#pragma unroll
            for (int h = 0; h < 2; h++) {
                int n = nRow[h];
                uint32_t off = (uint32_t)(n * 128 + ((cb ^ (n & 7)) << 4));
                ldsm4(bFh[2*h][0], bFh[2*h][1], bFh[2*h+1][0], bFh[2*h+1][1],
                      stb + 16384u + off);
                ldsm4(bFl[2*h][0], bFl[2*h][1], bFl[2*h+1][0], bFl[2*h+1][1],
                      stb + 32768u + off);
            }
#pragma unroll
            for (int mt = 0; mt < 4; mt++)
#pragma unroll
                for (int nt = 0; nt < 4; nt++) {
                    mma_bf16(acc[mt][nt], aFh[mt][0], aFh[mt][1], aFh[mt][2], aFh[mt][3],
                             bFh[nt][0], bFh[nt][1]);
                    mma_bf16(acc[mt][nt], aFh[mt][0], aFh[mt][1], aFh[mt][2], aFh[mt][3],
                             bFl[nt][0], bFl[nt][1]);
                    mma_bf16(acc[mt][nt], aFl[mt][0], aFl[mt][1], aFl[mt][2], aFl[mt][3],
                             bFh[nt][0], bFh[nt][1]);
                }
        }
        __syncthreads();
    }

    const size_t rowBase = (size_t)by * 64;
    const int    colBase = bx * 128 + warpN * 32;
#pragma unroll
    for (int mt = 0; mt < 4; mt++) {
        size_t r0 = rowBase + mt * 16 + g;
        size_t r1 = r0 + 8;
#pragma unroll
        for (int nt = 0; nt < 4; nt++) {
            int n = colBase + nt * 8 + 2 * tg;
            size_t i0 = r0 * N + n;
            size_t i1 = r1 * N + n;
            float2 v0 = make_float2(acc[mt][nt][0], acc[mt][nt][1]);
            float2 v1 = make_float2(acc[mt][nt][2], acc[mt][nt][3]);
            if (MODE == 1) {
                float2 q0 = *(const float2*)(R + i0);
                float2 q1 = *(const float2*)(R + i1);
                v0.x += q0.x; v0.y += q0.y;
                v1.x += q1.x; v1.y += q1.y;
            }
            *(float2*)(C + i0) = v0;
            *(float2*)(C + i1) = v1;
        }
    }
}

// ----------------------------------------------------------------------------
// fp16 GEMM (validated R12 config): C = A @ B. B single fp16.
// ASPLIT=2: A = hi+lo (2 MMA, exact A); ASPLIT=1: A single fp16 (1 MMA).
// CTA 64x128, 4 warps, 2-stage, 64KB smem, 2 CTAs/SM.
// MODE 0: C          MODE 1: C + R
// MODE 2: gate/up interleaved B -> silu(g)*u as SINGLE fp16 (row stride I_).
// MFAST: 1 -> mb=blockIdx.x (M fastest; lm_head DRAM streaming).
// ----------------------------------------------------------------------------
constexpr int STF_U32  = 8192;              // 32KB per stage (u32 units)
constexpr int TGF_SMEM = 2 * STF_U32 * 4;   // 64KB

template<int MODE, int MFAST, int ASPLIT>
__global__ __launch_bounds__(128, 2)
void tgf_kernel(const __half* __restrict__ Ah, const __half* __restrict__ Al,
                const __half* __restrict__ Bf,
                const float* __restrict__ R, float* __restrict__ C,
                __half* __restrict__ oh,
                int M, int N, int K)
{
    extern __shared__ uint32_t sm[];
    const uint32_t smem_b = (uint32_t)__cvta_generic_to_shared(sm);

    const int tid   = threadIdx.x;
    const int lane  = tid & 31;
    const int warpN = tid >> 5;
    const int g     = lane >> 2;
    const int tg    = lane & 3;
    const int rr    = lane & 7;
    const int ts    = lane >> 3;
    const int mb = MFAST ? blockIdx.x : blockIdx.y;
    const int nb = MFAST ? blockIdx.y : blockIdx.x;

    float acc[4][4][4];
#pragma unroll
    for (int a = 0; a < 4; a++)
#pragma unroll
        for (int b = 0; b < 4; b++)
#pragma unroll
            for (int c = 0; c < 4; c++) acc[a][b][c] = 0.f;

    const int nk = K >> 6;

    // per stage (u32): AsH[2048] AsL[2048] Bs[4096]
    auto fill = [&](int kt) {
        uint32_t* base = sm + (kt & 1) * STF_U32;
        const int k0 = kt * 64;
#pragma unroll
        for (int p = 0; p < 4; p++) {
            int i = tid + p * 128;
            int r = i >> 3, c = i & 7;
            int so = r * 32 + ((c ^ (r & 7)) << 2);
            size_t go = (size_t)(mb * 64 + r) * K + k0 + c * 8;
            cpa16(base + so, Ah + go);
            if (ASPLIT == 2) cpa16(base + 2048 + so, Al + go);
        }
#pragma unroll
        for (int p = 0; p < 8; p++) {
            int i = tid + p * 128;
            int r = i >> 3, c = i & 7;
            int so = r * 32 + ((c ^ (r & 7)) << 2);
            size_t go = (size_t)(nb * 128 + r) * K + k0 + c * 8;
            cpa16(base + 4096 + so, Bf + go);
        }
        cp_commit();
    };

    int mRow[4], nRow[2];
#pragma unroll
    for (int mt = 0; mt < 4; mt++) mRow[mt] = mt * 16 + ((ts & 1) << 3) + rr;
#pragma unroll
    for (int h = 0; h < 2; h++)    nRow[h]  = warpN * 32 + h * 16 + ((ts >> 1) << 3) + rr;
    const int khA = ts >> 1;
    const int khB = ts & 1;

    fill(0);

    for (int kt = 0; kt < nk; kt++) {
        if (kt + 1 < nk) {
            fill(kt + 1);
            cp_wait<1>();
        } else {
            cp_wait<0>();
        }
        __syncthreads();

        const uint32_t stb = smem_b + (uint32_t)(kt & 1) * 32768u;

#pragma unroll
        for (int ks = 0; ks < 4; ks++) {
            uint32_t aFh[4][4], aFl[4][4], bF[4][2];
            const int ca = 2 * ks + khA;
            const int cb = 2 * ks + khB;
#pragma unroll
            for (int mt = 0; mt < 4; mt++) {
                int m = mRow[mt];
                uint32_t off = (uint32_t)(m * 128 + ((ca ^ (m & 7)) << 4));
                ldsm4(aFh[mt][0], aFh[mt][1], aFh[mt][2], aFh[mt][3], stb + off);
                if (ASPLIT == 2)
                    ldsm4(aFl[mt][0], aFl[mt][1], aFl[mt][2], aFl[mt][3], stb + 8192u + off);
            }
#pragma unroll
            for (int h = 0; h < 2; h++) {
                int n = nRow[h];
                uint32_t off = (uint32_t)(n * 128 + ((cb ^ (n & 7)) << 4));
                ldsm4(bF[2*h][0], bF[2*h][1], bF[2*h+1][0], bF[2*h+1][1],
                      stb + 16384u + off);
            }
#pragma unroll
            for (int mt = 0; mt < 4; mt++)
#pragma unroll
                for (int nt = 0; nt < 4; nt++) {
                    mma_fp16(acc[mt][nt], aFh[mt][0], aFh[mt][1], aFh[mt][2], aFh[mt][3],
                             bF[nt][0], bF[nt][1]);
                    if (ASPLIT == 2)
                        mma_fp16(acc[mt][nt], aFl[mt][0], aFl[mt][1], aFl[mt][2], aFl[mt][3],
                                 bF[nt][0], bF[nt][1]);
                }
        }
        __syncthreads();
    }

    // ---- epilogue ----
    const size_t rowBase = (size_t)mb * 64;
    const int    colBase = nb * 128 + warpN * 32;
#pragma unroll
    for (int mt = 0; mt < 4; mt++) {
        size_t r0 = rowBase + mt * 16 + g;
        size_t r1 = r0 + 8;
#pragma unroll
        for (int nt = 0; nt < 4; nt++) {
            int n = colBase + nt * 8 + 2 * tg;
            if (MODE == 2) {
                size_t j = (size_t)(n >> 1);     // (gate, up) pair -> col j
                float g0 = acc[mt][nt][0], u0 = acc[mt][nt][1];
                float g1 = acc[mt][nt][2], u1 = acc[mt][nt][3];
                float v0 = g0 / (1.f + __expf(-g0)) * u0;
                float v1 = g1 / (1.f + __expf(-g1)) * u1;
                oh[r0 * I_ + j] = __float2half_rn(v0);
                oh[r1 * I_ + j] = __float2half_rn(v1);
            } else {
                size_t i0 = r0 * N + n;
                size_t i1 = r1 * N + n;
                float2 v0 = make_float2(acc[mt][nt][0], acc[mt][nt][1]);
                float2 v1 = make_float2(acc[mt][nt][2], acc[mt][nt][3]);
                if (MODE == 1) {
                    float2 q0 = *(const float2*)(R + i0);
                    float2 q1 = *(const float2*)(R + i1);
                    v0.x += q0.x; v0.y += q0.y;
                    v1.x += q1.x; v1.y += q1.y;
                }
                *(float2*)(C + i0) = v0;
                *(float2*)(C + i1) = v1;
            }
        }
    }
}

// ----------------------------------------------------------------------------
// Embedding gather
// ----------------------------------------------------------------------------
__global__ void embed_kernel(const int* __restrict__ ids,
                             const float* __restrict__ emb,
                             float* __restrict__ h)
{
    int t = blockIdx.x;
    int id = ids[t];
    const float4* src = (const float4*)(emb + (size_t)id * H_);
    float4* dst = (float4*)(h + (size_t)t * H_);
    for (int i = threadIdx.x; i < H_ / 4; i += blockDim.x) dst[i] = src[i];
}

// ----------------------------------------------------------------------------
// RMSNorm -> bf16 (hi, lo)
// ----------------------------------------------------------------------------
__global__ void rmsnorm_kernel(const float* __restrict__ h,
                               const float* __restrict__ w,
                               __nv_bfloat16* __restrict__ xh,
                               __nv_bfloat16* __restrict__ xl)
{
    int t = blockIdx.x;
    const float* hr = h + (size_t)t * H_;
    __shared__ float red[256];
    float s = 0.f;
    for (int i = threadIdx.x; i < H_; i += 256) { float v = hr[i]; s += v * v; }
    red[threadIdx.x] = s; __syncthreads();
    for (int st = 128; st > 0; st >>= 1) {
        if (threadIdx.x < st) red[threadIdx.x] += red[threadIdx.x + st];
        __syncthreads();
    }
    float scale = rsqrtf(red[0] / (float)H_ + 1e-5f);
    for (int i = threadIdx.x; i < H_; i += 256) {
        float v = hr[i] * scale * w[i];
        __nv_bfloat16 hi, lo; split_bf16(v, hi, lo);
        xh[(size_t)t * H_ + i] = hi;
        xl[(size_t)t * H_ + i] = lo;
    }
}

// RMSNorm -> fp16 (hi, lo)
__global__ void rmsnorm_fp16_kernel(const float* __restrict__ h,
                                    const float* __restrict__ w,
                                    __half* __restrict__ xh,
                                    __half* __restrict__ xl)
{
    int t = blockIdx.x;
    const float* hr = h + (size_t)t * H_;
    __shared__ float red[256];
    float s = 0.f;
    for (int i = threadIdx.x; i < H_; i += 256) { float v = hr[i]; s += v * v; }
    red[threadIdx.x] = s; __syncthreads();
    for (int st = 128; st > 0; st >>= 1) {
        if (threadIdx.x < st) red[threadIdx.x] += red[threadIdx.x + st];
        __syncthreads();
    }
    float scale = rsqrtf(red[0] / (float)H_ + 1e-5f);
    for (int i = threadIdx.x; i < H_; i += 256) {
        float v = hr[i] * scale * w[i];
        __half hi, lo; split_fp16(v, hi, lo);
        xh[(size_t)t * H_ + i] = hi;
        xl[(size_t)t * H_ + i] = lo;
    }
}

// ----------------------------------------------------------------------------
// Q/K prep: fused RoPE + Q-scale + bf16 hi/lo split
// ----------------------------------------------------------------------------
__global__ void qkprep_kernel(const float* __restrict__ qkv, const int* __restrict__ pos,
                              __nv_bfloat16* __restrict__ Qh, __nv_bfloat16* __restrict__ Ql,
                              __nv_bfloat16* __restrict__ Kh, __nv_bfloat16* __restrict__ Kl)
{
    int idx = blockIdx.x * blockDim.x + threadIdx.x;
    if (idx >= T_ * 24 * 64) return;
    int i    = idx & 63;
    int head = (idx >> 6) % 24;
    int t    = idx / (24 * 64);
    int b = t / S_, s = t % S_;

    float p = (float)pos[t];
    float e = ((float)i / 64.0f) * 13.28771237954945f;  // log2(10000)
    float inv = exp2f(-e);
    float ang = p * inv;
    float sn, cs;
    sincosf(ang, &sn, &cs);

    int off = (head < NH_) ? head * HD_ : KOFF_ + (head - NH_) * HD_;
    const float* v = qkv + (size_t)t * QKVN_ + off;
    float x1 = v[i], x2 = v[i + 64];
    float r1 = x1 * cs - x2 * sn;
    float r2 = x2 * cs + x1 * sn;

    __nv_bfloat16 *dh, *dl;
    if (head < NH_) {
        const float scale = 0.08838834764831845f;
        r1 *= scale; r2 *= scale;
        size_t base = (((size_t)(b * NH_ + head)) * S_ + s) * HD_;
        dh = Qh + base; dl = Ql + base;
    } else {
        size_t base = (((size_t)(b * NKV_ + head - NH_)) * S_ + s) * HD_;
        dh = Kh + base; dl = Kl + base;
    }
    __nv_bfloat16 h1, l1, h2, l2;
    split_bf16(r1, h1, l1);
    split_bf16(r2, h2, l2);
    dh[i] = h1;      dl[i] = l1;
    dh[i + 64] = h2; dl[i + 64] = l2;
}

// ----------------------------------------------------------------------------
// V prep: transpose to [B][NKV][HD][S] + bf16 hi/lo split
// ----------------------------------------------------------------------------
__global__ void vprep_kernel(const float* __restrict__ qkv,
                             __nv_bfloat16* __restrict__ Vth,
                             __nv_bfloat16* __restrict__ Vtl)
{
    __shared__ float tile[32][33];
    const int z = blockIdx.z;
    const int b = z / NKV_, hkv = z % NKV_;
    const int s0 = blockIdx.x * 32, d0 = blockIdx.y * 32;
    const int tx = threadIdx.x, ty = threadIdx.y;
#pragma unroll
    for (int r = ty; r < 32; r += 8)
        tile[r][tx] = qkv[(size_t)(b * S_ + s0 + r) * QKVN_ + VOFF_ + hkv * HD_ + d0 + tx];
    __syncthreads();
    size_t base = ((size_t)(b * NKV_ + hkv)) * HD_ * S_;
#pragma unroll
    for (int r = ty; r < 32; r += 8) {
        float v = tile[tx][r];
        __nv_bfloat16 hi, lo; split_bf16(v, hi, lo);
        size_t idx = base + (size_t)(d0 + r) * S_ + s0 + tx;
        Vth[idx] = hi;
        Vtl[idx] = lo;
    }
}

// ----------------------------------------------------------------------------
// Flash attention (validated R5 kernel, unchanged)
// ----------------------------------------------------------------------------
__global__ __launch_bounds__(128)
void flash_kernel(const __nv_bfloat16* __restrict__ Qh, const __nv_bfloat16* __restrict__ Ql,
                  const __nv_bfloat16* __restrict__ Kh, const __nv_bfloat16* __restrict__ Kl,
                  const __nv_bfloat16* __restrict__ Vth, const __nv_bfloat16* __restrict__ Vtl,
                  __nv_bfloat16* __restrict__ Oh, __nv_bfloat16* __restrict__ Ol)
{
    extern __shared__ uint32_t sm[];
    uint32_t* KsH = sm;
    uint32_t* KsL = sm + 4096;
    uint32_t* VsH = sm + 8192;
    uint32_t* VsL = sm + 12288;

    const int qt = (int)gridDim.x - 1 - (int)blockIdx.x;
    const int z  = blockIdx.y;
    const int b  = z >> 4, hq = z & 15, hkv = hq >> 1;

    const int tid  = threadIdx.x;
    const int lane = tid & 31;
    const int w    = tid >> 5;
    const int g    = lane >> 2;
    const int tg   = lane & 3;

    uint32_t qFh[8][4], qFl[8][4];
    {
        const uint32_t* qbh = (const uint32_t*)(Qh + (((size_t)(b * NH_ + hq)) * S_ + qt * 64 + w * 16) * HD_);
        const uint32_t* qbl = (const uint32_t*)(Ql + (((size_t)(b * NH_ + hq)) * S_ + qt * 64 + w * 16) * HD_);
#pragma unroll
        for (int ks = 0; ks < 8; ks++) {
            int c = 8 * ks + tg;
            qFh[ks][0] = qbh[g * 64 + c];
            qFh[ks][1] = qbh[(g + 8) * 64 + c];
            qFh[ks][2] = qbh[g * 64 + c + 4];
            qFh[ks][3] = qbh[(g + 8) * 64 + c + 4];
            qFl[ks][0] = qbl[g * 64 + c];
            qFl[ks][1] = qbl[(g + 8) * 64 + c];
            qFl[ks][2] = qbl[g * 64 + c + 4];
            qFl[ks][3] = qbl[(g + 8) * 64 + c + 4];
        }
    }

    float oAcc[16][4];
#pragma unroll
    for (int i = 0; i < 16; i++)
#pragma unroll
        for (int j = 0; j < 4; j++) oAcc[i][j] = 0.f;
    float mA = -1e30f, mB = -1e30f, lA = 0.f, lB = 0.f;

    const __nv_bfloat16* KgH = Kh  + ((size_t)(b * NKV_ + hkv)) * S_ * HD_;
    const __nv_bfloat16* KgL = Kl  + ((size_t)(b * NKV_ + hkv)) * S_ * HD_;
    const __nv_bfloat16* VgH = Vth + ((size_t)(b * NKV_ + hkv)) * HD_ * S_;
    const __nv_bfloat16* VgL = Vtl + ((size_t)(b * NKV_ + hkv)) * HD_ * S_;

    for (int kt = 0; kt <= qt; kt++) {
#pragma unroll
        for (int p = 0; p < 8; p++) {
            int i = tid + p * 128;
            int r = i >> 4, cc = i & 15;
            int dst = r * 64 + ((cc ^ (r & 7)) << 2);
            cpa16(KsH + dst, KgH + (size_t)(kt * 64 + r) * HD_ + cc * 8);
            cpa16(KsL + dst, KgL + (size_t)(kt * 64 + r) * HD_ + cc * 8);
        }
#pragma unroll
        for (int p = 0; p < 8; p++) {
            int i = tid + p * 128;
            int n = i >> 3, cc = i & 7;
            int dst = n * 32 + ((cc ^ (n & 7)) << 2);
            cpa16(VsH + dst, VgH + (size_t)n * S_ + kt * 64 + cc * 8);
            cpa16(VsL + dst, VgL + (size_t)n * S_ + kt * 64 + cc * 8);
        }
        cp_commit();
        cp_wait<0>();
        __syncthreads();

        float sAcc[8][4];
#pragma unroll
        for (int i = 0; i < 8; i++)
#pragma unroll
            for (int j = 0; j < 4; j++) sAcc[i][j] = 0.f;

#pragma unroll
        for (int ks = 0; ks < 8; ks++) {
            uint32_t kFh[8][2], kFl[8][2];
            const int c0 = 8 * ks + tg;
#pragma unroll
            for (int nt = 0; nt < 8; nt++) {
                int key = nt * 8 + g;
                int sw = (key & 7) << 2;
                int o0 = key * 64 + (c0 ^ sw);
                int o1 = key * 64 + ((c0 + 4) ^ sw);
                kFh[nt][0] = KsH[o0]; kFh[nt][1] = KsH[o1];
                kFl[nt][0] = KsL[o0]; kFl[nt][1] = KsL[o1];
            }
#pragma unroll
            for (int nt = 0; nt < 8; nt++) {
                mma_bf16(sAcc[nt], qFh[ks][0], qFh[ks][1], qFh[ks][2], qFh[ks][3],
                         kFh[nt][0], kFh[nt][1]);
                mma_bf16(sAcc[nt], qFh[ks][0], qFh[ks][1], qFh[ks][2], qFh[ks][3],
                         kFl[nt][0], kFl[nt][1]);
                mma_bf16(sAcc[nt], qFl[ks][0], qFl[ks][1], qFl[ks][2], qFl[ks][3],
                         kFh[nt][0], kFh[nt][1]);
            }
        }

        if (kt == qt) {
            const int qrA = w * 16 + g, qrB = qrA + 8;
#pragma unroll
            for (int nt = 0; nt < 8; nt++) {
                int k0 = nt * 8 + 2 * tg, k1 = k0 + 1;
                if (k0 > qrA) sAcc[nt][0] = -1e30f;
                if (k1 > qrA) sAcc[nt][1] = -1e30f;
                if (k0 > qrB) sAcc[nt][2] = -1e30f;
                if (k1 > qrB) sAcc[nt][3] = -1e30f;
            }
        }

        float tmA = -1e30f, tmB = -1e30f;
#pragma unroll
        for (int nt = 0; nt < 8; nt++) {
            tmA = fmaxf(tmA, fmaxf(sAcc[nt][0], sAcc[nt][1]));
            tmB = fmaxf(tmB, fmaxf(sAcc[nt][2], sAcc[nt][3]));
        }
        tmA = fmaxf(tmA, __shfl_xor_sync(0xffffffff, tmA, 1));
        tmA = fmaxf(tmA, __shfl_xor_sync(0xffffffff, tmA, 2));
        tmB = fmaxf(tmB, __shfl_xor_sync(0xffffffff, tmB, 1));
        tmB = fmaxf(tmB, __shfl_xor_sync(0xffffffff, tmB, 2));
        float nmA = fmaxf(mA, tmA), nmB = fmaxf(mB, tmB);
        float eA = __expf(mA - nmA), eB = __expf(mB - nmB);

        float rsA = 0.f, rsB = 0.f;
#pragma unroll
        for (int nt = 0; nt < 8; nt++) {
            sAcc[nt][0] = __expf(sAcc[nt][0] - nmA);
            sAcc[nt][1] = __expf(sAcc[nt][1] - nmA);
            sAcc[nt][2] = __expf(sAcc[nt][2] - nmB);
            sAcc[nt][3] = __expf(sAcc[nt][3] - nmB);
            rsA += sAcc[nt][0] + sAcc[nt][1];
            rsB += sAcc[nt][2] + sAcc[nt][3];
        }
        rsA += __shfl_xor_sync(0xffffffff, rsA, 1);
        rsA += __shfl_xor_sync(0xffffffff, rsA, 2);
        rsB += __shfl_xor_sync(0xffffffff, rsB, 1);
        rsB += __shfl_xor_sync(0xffffffff, rsB, 2);
        lA = lA * eA + rsA;
        lB = lB * eB + rsB;
        mA = nmA; mB = nmB;
#pragma unroll
        for (int nt = 0; nt < 16; nt++) {
            oAcc[nt][0] *= eA; oAcc[nt][1] *= eA;
            oAcc[nt][2] *= eB; oAcc[nt][3] *= eB;
        }

#pragma unroll
        for (int ks2 = 0; ks2 < 4; ks2++) {
            uint32_t ph[4], pl[4];
#pragma unroll
            for (int q = 0; q < 2; q++) {
                const float* s4 = sAcc[2 * ks2 + q];
                uint32_t hp0 = pack_bf16x2(s4[0], s4[1]);
                uint32_t hp1 = pack_bf16x2(s4[2], s4[3]);
                float h00 = __uint_as_float(hp0 << 16);
                float h01 = __uint_as_float(hp0 & 0xFFFF0000u);
                float h10 = __uint_as_float(hp1 << 16);
                float h11 = __uint_as_float(hp1 & 0xFFFF0000u);
                ph[2 * q]     = hp0;
                ph[2 * q + 1] = hp1;
                pl[2 * q]     = pack_bf16x2(s4[0] - h00, s4[1] - h01);
                pl[2 * q + 1] = pack_bf16x2(s4[2] - h10, s4[3] - h11);
            }
            const int kp = 8 * ks2 + tg;
#pragma unroll
            for (int nt2 = 0; nt2 < 16; nt2++) {
                int n = nt2 * 8 + g;
                int sw = (n & 7) << 2;
                int o0 = n * 32 + (kp ^ sw);
                int o1 = n * 32 + ((kp + 4) ^ sw);
                uint32_t v0h = VsH[o0], v1h = VsH[o1];
                uint32_t v0l = VsL[o0], v1l = VsL[o1];
                mma_bf16(oAcc[nt2], ph[0], ph[1], ph[2], ph[3], v0h, v1h);
                mma_bf16(oAcc[nt2], ph[0], ph[1], ph[2], ph[3], v0l, v1l);
                mma_bf16(oAcc[nt2], pl[0], pl[1], pl[2], pl[3], v0h, v1h);
            }
        }
        __syncthreads();
    }

    const float ilA = 1.f / lA, ilB = 1.f / lB;
    const size_t tA = (size_t)b * S_ + qt * 64 + w * 16 + g;
    const size_t tB = tA + 8;
#pragma unroll
    for (int nt2 = 0; nt2 < 16; nt2++) {
        int col = hq * HD_ + nt2 * 8 + 2 * tg;
        float a0 = oAcc[nt2][0] * ilA, a1 = oAcc[nt2][1] * ilA;
        float b0 = oAcc[nt2][2] * ilB, b1 = oAcc[nt2][3] * ilB;

        uint32_t ahp = pack_bf16x2(a0, a1);
        uint32_t bhp = pack_bf16x2(b0, b1);
        float ah0 = __uint_as_float(ahp << 16), ah1 = __uint_as_float(ahp & 0xFFFF0000u);
        float bh0 = __uint_as_float(bhp << 16), bh1 = __uint_as_float(bhp & 0xFFFF0000u);
        uint32_t alp = pack_bf16x2(a0 - ah0, a1 - ah1);
        uint32_t blp = pack_bf16x2(b0 - bh0, b1 - bh1);

        *(uint32_t*)(Oh + tA * H_ + col) = ahp;
        *(uint32_t*)(Ol + tA * H_ + col) = alp;
        *(uint32_t*)(Oh + tB * H_ + col) = bhp;
        *(uint32_t*)(Ol + tB * H_ + col) = blp;
    }
}

// ----------------------------------------------------------------------------
// Host orchestration
// ----------------------------------------------------------------------------
extern "C" void kernel_launch(void* const* d_in, const int* in_sizes, int n_in,
                              void* d_out, int out_size)
{
    (void)in_sizes; (void)n_in; (void)out_size;
    const int*   ids    = (const int*)  d_in[0];
    const int*   pos    = (const int*)  d_in[1];
    const float* emb    = (const float*)d_in[2];
    const float* Wqkv   = (const float*)d_in[3];
    const float* Wo     = (const float*)d_in[4];
    const float* Wgu    = (const float*)d_in[5];
    const float* Wdn    = (const float*)d_in[6];
    const float* ln1    = (const float*)d_in[7];
    const float* ln2    = (const float*)d_in[8];
    const float* normw  = (const float*)d_in[9];
    const float* lmhead = (const float*)d_in[10];
    float* out = (float*)d_out;

    cudaFuncSetAttribute(tg_kernel<0>, cudaFuncAttributeMaxDynamicSharedMemorySize, TG_SMEM);
    cudaFuncSetAttribute(tg_kernel<1>, cudaFuncAttributeMaxDynamicSharedMemorySize, TG_SMEM);
    cudaFuncSetAttribute((const void*)tgf_kernel<0,1,1>, cudaFuncAttributeMaxDynamicSharedMemorySize, TGF_SMEM);
    cudaFuncSetAttribute((const void*)tgf_kernel<1,0,1>, cudaFuncAttributeMaxDynamicSharedMemorySize, TGF_SMEM);
    cudaFuncSetAttribute((const void*)tgf_kernel<2,0,1>, cudaFuncAttributeMaxDynamicSharedMemorySize, TGF_SMEM);
    cudaFuncSetAttribute(flash_kernel, cudaFuncAttributeMaxDynamicSharedMemorySize, 65536);

    float *h, *qkv;
    __nv_bfloat16 *x, *xl, *attn, *attnl, *si, *wh, *wl;
    __nv_bfloat16 *qh, *ql, *kh, *kl, *vth, *vtl;
    cudaGetSymbolAddress((void**)&h,     g_h);
    cudaGetSymbolAddress((void**)&x,     g_x);
    cudaGetSymbolAddress((void**)&xl,    g_xl);
    cudaGetSymbolAddress((void**)&qkv,   g_qkv);
    cudaGetSymbolAddress((void**)&attn,  g_attn);
    cudaGetSymbolAddress((void**)&attnl, g_attnl);
    cudaGetSymbolAddress((void**)&si,    g_si);
    cudaGetSymbolAddress((void**)&wh,    g_wh);
    cudaGetSymbolAddress((void**)&wl,    g_wl);
    cudaGetSymbolAddress((void**)&qh,    g_qh);
    cudaGetSymbolAddress((void**)&ql,    g_ql);
    cudaGetSymbolAddress((void**)&kh,    g_kh);
    cudaGetSymbolAddress((void**)&kl,    g_kl);
    cudaGetSymbolAddress((void**)&vth,   g_vth);
    cudaGetSymbolAddress((void**)&vtl,   g_vtl);

    embed_kernel<<<T_, 256>>>(ids, emb, h);

    for (int l = 0; l < L_; l++) {
        const float* wqkv = Wqkv + (size_t)l * H_ * QKVN_;
        const float* wo   = Wo   + (size_t)l * H_ * H_;
        const float* wgu  = Wgu  + (size_t)l * H_ * (2 * I_);
        const float* wdn  = Wdn  + (size_t)l * I_ * H_;

        // ---- attention block (bf16 3-MMA, validated) ----
        rmsnorm_kernel<<<T_, 256>>>(h, ln1 + (size_t)l * H_, x, xl);
        wsplit_t_kernel<<<dim3(QKVN_ / 32, H_ / 32), dim3(32, 8)>>>(wqkv, wh, wl, H_, QKVN_, 0, 1, 0);
        tg_kernel<0><<<dim3(QKVN_ / 128, T_ / 64), 128, TG_SMEM>>>(x, xl, wh, wl, nullptr, qkv,
                                                                   T_, QKVN_, H_);

        {
            int tot = T_ * 24 * 64;
            qkprep_kernel<<<(tot + 255) / 256, 256>>>(qkv, pos, qh, ql, kh, kl);
        }
        vprep_kernel<<<dim3(S_ / 32, HD_ / 32, B_ * NKV_), dim3(32, 8)>>>(qkv, vth, vtl);

        flash_kernel<<<dim3(S_ / 64, B_ * NH_), 128, 65536>>>(qh, ql, kh, kl, vth, vtl,
                                                              attn, attnl);

        wsplit_t_kernel<<<dim3(H_ / 32, H_ / 32), dim3(32, 8)>>>(wo, wh, wl, H_, H_, 0, 1, 0);
        tg_kernel<1><<<dim3(H_ / 128, T_ / 64), 128, TG_SMEM>>>(attn, attnl, wh, wl, h, h,
                                                                T_, H_, H_);

        // ---- MLP block (fp16; gate-up single-A 1-MMA, down-proj single-A 1-MMA) ----
        rmsnorm_fp16_kernel<<<T_, 256>>>(h, ln2 + (size_t)l * H_, (__half*)x, (__half*)xl);
        wsplit_t_fp16_kernel<<<dim3(I_ / 32, H_ / 32), dim3(32, 8)>>>(wgu, (__half*)wh,
                                                                      H_, 2 * I_, 0, 2, 0);
        wsplit_t_fp16_kernel<<<dim3(I_ / 32, H_ / 32), dim3(32, 8)>>>(wgu, (__half*)wh,
                                                                      H_, 2 * I_, I_, 2, 1);
        tgf_kernel<2, 0, 1><<<dim3(2 * I_ / 128, T_ / 64), 128, TGF_SMEM>>>(
            (const __half*)x, nullptr, (const __half*)wh,
            nullptr, nullptr, (__half*)si, T_, 2 * I_, H_);

        wsplit_t_fp16_kernel<<<dim3(H_ / 32, I_ / 32), dim3(32, 8)>>>(wdn, (__half*)wh,
                                                                      I_, H_, 0, 1, 0);
        tgf_kernel<1, 0, 1><<<dim3(H_ / 128, T_ / 64), 128, TGF_SMEM>>>(
            (const __half*)si, nullptr, (const __half*)wh,
            h, h, nullptr, T_, H_, I_);
    }

    // ---- final norm + fully-fp16 1-MMA lm_head (M-fastest: stream 128MB B once) ----
    rmsnorm_fp16_kernel<<<T_, 256>>>(h, normw, (__half*)x, (__half*)xl);
    wsplit_t_fp16_kernel<<<dim3(VOCAB_ / 32, H_ / 32), dim3(32, 8)>>>(lmhead, (__half*)wh,
                                                                      H_, VOCAB_, 0, 1, 0);
    tgf_kernel<0, 1, 1><<<dim3(T_ / 64, VOCAB_ / 128), 128, TGF_SMEM>>>(
        (const __half*)x, (const __half*)xl, (const __half*)wh,
        nullptr, out, nullptr, T_, VOCAB_, H_);
}

// round 17
// speedup vs baseline: 1.3366x; 1.0002x over previous
#include <cuda_runtime.h>
#include <cuda_bf16.h>
#include <cuda_fp16.h>
#include <math.h>
#include <stdint.h>

// ----------------------------------------------------------------------------
// Model constants
// ----------------------------------------------------------------------------
constexpr int B_    = 2;
constexpr int S_    = 2048;
constexpr int T_    = B_ * S_;        // 4096 tokens
constexpr int H_    = 2048;
constexpr int NH_   = 16;
constexpr int NKV_  = 8;
constexpr int HD_   = 128;
constexpr int I_    = 5632;
constexpr int L_    = 2;
constexpr int VOCAB_= 32000;
constexpr int QKVN_ = (NH_ + 2 * NKV_) * HD_;  // 4096
constexpr int KOFF_ = NH_ * HD_;               // 2048
constexpr int VOFF_ = KOFF_ + NKV_ * HD_;      // 3072

// ----------------------------------------------------------------------------
// Scratch (device globals: allocation-free rule)
// ----------------------------------------------------------------------------
__device__ float          g_h    [(size_t)T_ * H_];
__device__ __nv_bfloat16  g_x    [(size_t)T_ * H_];
__device__ __nv_bfloat16  g_xl   [(size_t)T_ * H_];
__device__ float          g_qkv  [(size_t)T_ * QKVN_];
__device__ __nv_bfloat16  g_attn [(size_t)T_ * H_];
__device__ __nv_bfloat16  g_attnl[(size_t)T_ * H_];
__device__ __nv_bfloat16  g_si   [(size_t)T_ * I_];
__device__ __nv_bfloat16  g_wh   [(size_t)H_ * VOCAB_];  // weight staging (hi / fp16)
__device__ __nv_bfloat16  g_wl   [(size_t)H_ * VOCAB_];  // lo
// flash-attention operands
__device__ __nv_bfloat16  g_qh [(size_t)B_ * NH_  * S_ * HD_];
__device__ __nv_bfloat16  g_ql [(size_t)B_ * NH_  * S_ * HD_];
__device__ __nv_bfloat16  g_kh [(size_t)B_ * NKV_ * S_ * HD_];
__device__ __nv_bfloat16  g_kl [(size_t)B_ * NKV_ * S_ * HD_];
__device__ __nv_bfloat16  g_vth[(size_t)B_ * NKV_ * HD_ * S_];
__device__ __nv_bfloat16  g_vtl[(size_t)B_ * NKV_ * HD_ * S_];

// ----------------------------------------------------------------------------
// helpers
// ----------------------------------------------------------------------------
__device__ __forceinline__ void split_bf16(float v, __nv_bfloat16& hi, __nv_bfloat16& lo) {
    hi = __float2bfloat16(v);
    lo = __float2bfloat16(v - __bfloat162float(hi));
}

__device__ __forceinline__ void split_fp16(float v, __half& hi, __half& lo) {
    hi = __float2half_rn(v);
    lo = __float2half_rn(v - __half2float(hi));
}

__device__ __forceinline__ uint32_t pack_bf16x2(float x, float y) {
    __nv_bfloat162 t = __float22bfloat162_rn(make_float2(x, y));
    uint32_t u; memcpy(&u, &t, 4);
    return u;
}

__device__ __forceinline__ void mma_bf16(float c[4],
                                         uint32_t a0, uint32_t a1, uint32_t a2, uint32_t a3,
                                         uint32_t b0, uint32_t b1)
{
    asm volatile(
        "mma.sync.aligned.m16n8k16.row.col.f32.bf16.bf16.f32 "
        "{%0,%1,%2,%3}, {%4,%5,%6,%7}, {%8,%9}, {%0,%1,%2,%3};\n"
        : "+f"(c[0]), "+f"(c[1]), "+f"(c[2]), "+f"(c[3])
        : "r"(a0), "r"(a1), "r"(a2), "r"(a3), "r"(b0), "r"(b1));
}

__device__ __forceinline__ void mma_fp16(float c[4],
                                         uint32_t a0, uint32_t a1, uint32_t a2, uint32_t a3,
                                         uint32_t b0, uint32_t b1)
{
    asm volatile(
        "mma.sync.aligned.m16n8k16.row.col.f32.f16.f16.f32 "
        "{%0,%1,%2,%3}, {%4,%5,%6,%7}, {%8,%9}, {%0,%1,%2,%3};\n"
        : "+f"(c[0]), "+f"(c[1]), "+f"(c[2]), "+f"(c[3])
        : "r"(a0), "r"(a1), "r"(a2), "r"(a3), "r"(b0), "r"(b1));
}

__device__ __forceinline__ void ldsm4(uint32_t& r0, uint32_t& r1, uint32_t& r2, uint32_t& r3,
                                      uint32_t addr)
{
    asm volatile("ldmatrix.sync.aligned.m8n8.x4.shared.b16 {%0,%1,%2,%3}, [%4];"
                 : "=r"(r0), "=r"(r1), "=r"(r2), "=r"(r3) : "r"(addr));
}

__device__ __forceinline__ void cpa16(uint32_t* smem, const void* g) {
    uint32_t s = (uint32_t)__cvta_generic_to_shared(smem);
    asm volatile("cp.async.cg.shared.global [%0], [%1], 16;\n" :: "r"(s), "l"(g));
}
__device__ __forceinline__ void cp_commit() {
    asm volatile("cp.async.commit_group;\n");
}
template<int N>
__device__ __forceinline__ void cp_wait() {
    asm volatile("cp.async.wait_group %0;\n" :: "n"(N));
}

// ----------------------------------------------------------------------------
// Weight split + transpose: W[K][N] fp32 -> [N][K] bf16 hi/lo.
// 64(K) x 32(N) tiles; paired bf16x2 stores (128B/warp coalesced writes).
// Remap: staged row = rmul*n + roff, src col = coff + n.
// ----------------------------------------------------------------------------
__global__ void wsplit_t_kernel(const float* __restrict__ W,
                                __nv_bfloat16* __restrict__ th,
                                __nv_bfloat16* __restrict__ tl,
                                int K, int Nsrc, int coff, int rmul, int roff)
{
    __shared__ float tile[64][33];
    const int n0 = blockIdx.x * 32, k0 = blockIdx.y * 64;
    const int tx = threadIdx.x, ty = threadIdx.y;
#pragma unroll
    for (int r = ty; r < 64; r += 8)
        tile[r][tx] = W[(size_t)(k0 + r) * Nsrc + coff + n0 + tx];
    __syncthreads();
#pragma unroll
    for (int rr = ty; rr < 32; rr += 8) {
        float v0 = tile[2 * tx][rr];
        float v1 = tile[2 * tx + 1][rr];
        __nv_bfloat16 h0, l0, h1, l1;
        split_bf16(v0, h0, l0);
        split_bf16(v1, h1, l1);
        size_t row = (size_t)rmul * (n0 + rr) + roff;
        size_t idx = row * K + k0 + 2 * tx;
        __nv_bfloat162 hp; hp.x = h0; hp.y = h1;
        __nv_bfloat162 lp; lp.x = l0; lp.y = l1;
        *(__nv_bfloat162*)(th + idx) = hp;
        *(__nv_bfloat162*)(tl + idx) = lp;
    }
}

// Weight transpose to SINGLE fp16, 64x32 tiles, half2 stores.
// blockIdx.z remap (for merged gate/up staging): coff += z*czoff, roff += z*rzoff.
__global__ void wsplit_t_fp16_kernel(const float* __restrict__ W,
                                     __half* __restrict__ th,
                                     int K, int Nsrc, int coff, int rmul, int roff,
                                     int czoff, int rzoff)
{
    const int z = (int)blockIdx.z;
    const int cofz = coff + z * czoff;
    const int rofz = roff + z * rzoff;
    __shared__ float tile[64][33];
    const int n0 = blockIdx.x * 32, k0 = blockIdx.y * 64;
    const int tx = threadIdx.x, ty = threadIdx.y;
#pragma unroll
    for (int r = ty; r < 64; r += 8)
        tile[r][tx] = W[(size_t)(k0 + r) * Nsrc + cofz + n0 + tx];
    __syncthreads();
#pragma unroll
    for (int rr = ty; rr < 32; rr += 8) {
        float v0 = tile[2 * tx][rr];
        float v1 = tile[2 * tx + 1][rr];
        size_t row = (size_t)rmul * (n0 + rr) + rofz;
        size_t idx = row * K + k0 + 2 * tx;
        __half2 hp;
        hp.x = __float2half_rn(v0);
        hp.y = __float2half_rn(v1);
        *(__half2*)(th + idx) = hp;
    }
}

// ----------------------------------------------------------------------------
// bf16 2-split 3-MMA GEMM (qkv / o-proj). CTA 64x128, 4 warps, 2 CTAs/SM.
// MODE 0: C = A@B   MODE 1: C = A@B + R
// ----------------------------------------------------------------------------
constexpr int ST_U32  = 12288;              // 48KB per stage (u32 units)
constexpr int TG_SMEM = 2 * ST_U32 * 4;     // 96KB

template<int MODE>
__global__ __launch_bounds__(128, 2)
void tg_kernel(const __nv_bfloat16* __restrict__ Ah, const __nv_bfloat16* __restrict__ Al,
               const __nv_bfloat16* __restrict__ Bh, const __nv_bfloat16* __restrict__ Bl,
               const float* __restrict__ R, float* __restrict__ C,
               int M, int N, int K)
{
    extern __shared__ uint32_t sm[];
    const uint32_t smem_b = (uint32_t)__cvta_generic_to_shared(sm);

    const int tid   = threadIdx.x;
    const int lane  = tid & 31;
    const int warpN = tid >> 5;
    const int g     = lane >> 2;
    const int tg    = lane & 3;
    const int rr    = lane & 7;
    const int ts    = lane >> 3;
    const int bx = blockIdx.x, by = blockIdx.y;

    float acc[4][4][4];
#pragma unroll
    for (int a = 0; a < 4; a++)
#pragma unroll
        for (int b = 0; b < 4; b++)
#pragma unroll
            for (int c = 0; c < 4; c++) acc[a][b][c] = 0.f;

    const int nk = K >> 6;

    auto fill = [&](int kt) {
        uint32_t* base = sm + (kt & 1) * ST_U32;
        const int k0 = kt * 64;
#pragma unroll
        for (int p = 0; p < 4; p++) {
            int i = tid + p * 128;
            int r = i >> 3, c = i & 7;
            int so = r * 32 + ((c ^ (r & 7)) << 2);
            size_t go = (size_t)(by * 64 + r) * K + k0 + c * 8;
            cpa16(base        + so, Ah + go);
            cpa16(base + 2048 + so, Al + go);
        }
#pragma unroll
        for (int p = 0; p < 8; p++) {
            int i = tid + p * 128;
            int r = i >> 3, c = i & 7;
            int so = r * 32 + ((c ^ (r & 7)) << 2);
            size_t go = (size_t)(bx * 128 + r) * K + k0 + c * 8;
            cpa16(base + 4096 + so, Bh + go);
            cpa16(base + 8192 + so, Bl + go);
        }
        cp_commit();
    };

    int mRow[4], nRow[2];
#pragma unroll
    for (int mt = 0; mt < 4; mt++) mRow[mt] = mt * 16 + ((ts & 1) << 3) + rr;
#pragma unroll
    for (int h = 0; h < 2; h++)    nRow[h]  = warpN * 32 + h * 16 + ((ts >> 1) << 3) + rr;
    const int khA = ts >> 1;
    const int khB = ts & 1;

    fill(0);

    for (int kt = 0; kt < nk; kt++) {
        if (kt + 1 < nk) {
            fill(kt + 1);
            cp_wait<1>();
        } else {
            cp_wait<0>();
        }
        __syncthreads();

        const uint32_t stb = smem_b + (uint32_t)(kt & 1) * 49152u;

#pragma unroll
        for (int ks = 0; ks < 4; ks++) {
            uint32_t aFh[4][4], aFl[4][4], bFh[4][2], bFl[4][2];
            const int ca = 2 * ks + khA;
            const int cb = 2 * ks + khB;
#pragma unroll
            for (int mt = 0; mt < 4; mt++) {
                int m = mRow[mt];
                uint32_t off = (uint32_t)(m * 128 + ((ca ^ (m & 7)) << 4));
                ldsm4(aFh[mt][0], aFh[mt][1], aFh[mt][2], aFh[mt][3], stb + off);
                ldsm4(aFl[mt][0], aFl[mt][1], aFl[mt][2], aFl[mt][3], stb + 8192u + off);
            }
#pragma unroll
            for (int h = 0; h < 2; h++) {
                int n = nRow[h];
                uint32_t off = (uint32_t)(n * 128 + ((cb ^ (n & 7)) << 4));
                ldsm4(bFh[2*h][0], bFh[2*h][1], bFh[2*h+1][0], bFh[2*h+1][1],
                      stb + 16384u + off);
                ldsm4(bFl[2*h][0], bFl[2*h][1], bFl[2*h+1][0], bFl[2*h+1][1],
                      stb + 32768u + off);
            }
#pragma unroll
            for (int mt = 0; mt < 4; mt++)
#pragma unroll
                for (int nt = 0; nt < 4; nt++) {
                    mma_bf16(acc[mt][nt], aFh[mt][0], aFh[mt][1], aFh[mt][2], aFh[mt][3],
                             bFh[nt][0], bFh[nt][1]);
                    mma_bf16(acc[mt][nt], aFh[mt][0], aFh[mt][1], aFh[mt][2], aFh[mt][3],
                             bFl[nt][0], bFl[nt][1]);
                    mma_bf16(acc[mt][nt], aFl[mt][0], aFl[mt][1], aFl[mt][2], aFl[mt][3],
                             bFh[nt][0], bFh[nt][1]);
                }
        }
        __syncthreads();
    }

    const size_t rowBase = (size_t)by * 64;
    const int    colBase = bx * 128 + warpN * 32;
#pragma unroll
    for (int mt = 0; mt < 4; mt++) {
        size_t r0 = rowBase + mt * 16 + g;
        size_t r1 = r0 + 8;
#pragma unroll
        for (int nt = 0; nt < 4; nt++) {
            int n = colBase + nt * 8 + 2 * tg;
            size_t i0 = r0 * N + n;
            size_t i1 = r1 * N + n;
            float2 v0 = make_float2(acc[mt][nt][0], acc[mt][nt][1]);
            float2 v1 = make_float2(acc[mt][nt][2], acc[mt][nt][3]);
            if (MODE == 1) {
                float2 q0 = *(const float2*)(R + i0);
                float2 q1 = *(const float2*)(R + i1);
                v0.x += q0.x; v0.y += q0.y;
                v1.x += q1.x; v1.y += q1.y;
            }
            *(float2*)(C + i0) = v0;
            *(float2*)(C + i1) = v1;
        }
    }
}

// ----------------------------------------------------------------------------
// fp16 GEMM (validated R12 config): C = A @ B. B single fp16.
// ASPLIT=2: A = hi+lo (2 MMA, exact A); ASPLIT=1: A single fp16 (1 MMA).
// CTA 64x128, 4 warps, 2-stage, 64KB smem, 2 CTAs/SM.
// MODE 0: C          MODE 1: C + R
// MODE 2: gate/up interleaved B -> silu(g)*u as SINGLE fp16 (row stride I_).
// MFAST: 1 -> mb=blockIdx.x (M fastest; lm_head DRAM streaming).
// ----------------------------------------------------------------------------
constexpr int STF_U32  = 8192;              // 32KB per stage (u32 units)
constexpr int TGF_SMEM = 2 * STF_U32 * 4;   // 64KB

template<int MODE, int MFAST, int ASPLIT>
__global__ __launch_bounds__(128, 2)
void tgf_kernel(const __half* __restrict__ Ah, const __half* __restrict__ Al,
                const __half* __restrict__ Bf,
                const float* __restrict__ R, float* __restrict__ C,
                __half* __restrict__ oh,
                int M, int N, int K)
{
    extern __shared__ uint32_t sm[];
    const uint32_t smem_b = (uint32_t)__cvta_generic_to_shared(sm);

    const int tid   = threadIdx.x;
    const int lane  = tid & 31;
    const int warpN = tid >> 5;
    const int g     = lane >> 2;
    const int tg    = lane & 3;
    const int rr    = lane & 7;
    const int ts    = lane >> 3;
    const int mb = MFAST ? blockIdx.x : blockIdx.y;
    const int nb = MFAST ? blockIdx.y : blockIdx.x;

    float acc[4][4][4];
#pragma unroll
    for (int a = 0; a < 4; a++)
#pragma unroll
        for (int b = 0; b < 4; b++)
#pragma unroll
            for (int c = 0; c < 4; c++) acc[a][b][c] = 0.f;

    const int nk = K >> 6;

    // per stage (u32): AsH[2048] AsL[2048] Bs[4096]
    auto fill = [&](int kt) {
        uint32_t* base = sm + (kt & 1) * STF_U32;
        const int k0 = kt * 64;
#pragma unroll
        for (int p = 0; p < 4; p++) {
            int i = tid + p * 128;
            int r = i >> 3, c = i & 7;
            int so = r * 32 + ((c ^ (r & 7)) << 2);
            size_t go = (size_t)(mb * 64 + r) * K + k0 + c * 8;
            cpa16(base + so, Ah + go);
            if (ASPLIT == 2) cpa16(base + 2048 + so, Al + go);
        }
#pragma unroll
        for (int p = 0; p < 8; p++) {
            int i = tid + p * 128;
            int r = i >> 3, c = i & 7;
            int so = r * 32 + ((c ^ (r & 7)) << 2);
            size_t go = (size_t)(nb * 128 + r) * K + k0 + c * 8;
            cpa16(base + 4096 + so, Bf + go);
        }
        cp_commit();
    };

    int mRow[4], nRow[2];
#pragma unroll
    for (int mt = 0; mt < 4; mt++) mRow[mt] = mt * 16 + ((ts & 1) << 3) + rr;
#pragma unroll
    for (int h = 0; h < 2; h++)    nRow[h]  = warpN * 32 + h * 16 + ((ts >> 1) << 3) + rr;
    const int khA = ts >> 1;
    const int khB = ts & 1;

    fill(0);

    for (int kt = 0; kt < nk; kt++) {
        if (kt + 1 < nk) {
            fill(kt + 1);
            cp_wait<1>();
        } else {
            cp_wait<0>();
        }
        __syncthreads();

        const uint32_t stb = smem_b + (uint32_t)(kt & 1) * 32768u;

#pragma unroll
        for (int ks = 0; ks < 4; ks++) {
            uint32_t aFh[4][4], aFl[4][4], bF[4][2];
            const int ca = 2 * ks + khA;
            const int cb = 2 * ks + khB;
#pragma unroll
            for (int mt = 0; mt < 4; mt++) {
                int m = mRow[mt];
                uint32_t off = (uint32_t)(m * 128 + ((ca ^ (m & 7)) << 4));
                ldsm4(aFh[mt][0], aFh[mt][1], aFh[mt][2], aFh[mt][3], stb + off);
                if (ASPLIT == 2)
                    ldsm4(aFl[mt][0], aFl[mt][1], aFl[mt][2], aFl[mt][3], stb + 8192u + off);
            }
#pragma unroll
            for (int h = 0; h < 2; h++) {
                int n = nRow[h];
                uint32_t off = (uint32_t)(n * 128 + ((cb ^ (n & 7)) << 4));
                ldsm4(bF[2*h][0], bF[2*h][1], bF[2*h+1][0], bF[2*h+1][1],
                      stb + 16384u + off);
            }
#pragma unroll
            for (int mt = 0; mt < 4; mt++)
#pragma unroll
                for (int nt = 0; nt < 4; nt++) {
                    mma_fp16(acc[mt][nt], aFh[mt][0], aFh[mt][1], aFh[mt][2], aFh[mt][3],
                             bF[nt][0], bF[nt][1]);
                    if (ASPLIT == 2)
                        mma_fp16(acc[mt][nt], aFl[mt][0], aFl[mt][1], aFl[mt][2], aFl[mt][3],
                                 bF[nt][0], bF[nt][1]);
                }
        }
        __syncthreads();
    }

    // ---- epilogue ----
    const size_t rowBase = (size_t)mb * 64;
    const int    colBase = nb * 128 + warpN * 32;
#pragma unroll
    for (int mt = 0; mt < 4; mt++) {
        size_t r0 = rowBase + mt * 16 + g;
        size_t r1 = r0 + 8;
#pragma unroll
        for (int nt = 0; nt < 4; nt++) {
            int n = colBase + nt * 8 + 2 * tg;
            if (MODE == 2) {
                size_t j = (size_t)(n >> 1);     // (gate, up) pair -> col j
                float g0 = acc[mt][nt][0], u0 = acc[mt][nt][1];
                float g1 = acc[mt][nt][2], u1 = acc[mt][nt][3];
                float v0 = g0 / (1.f + __expf(-g0)) * u0;
                float v1 = g1 / (1.f + __expf(-g1)) * u1;
                oh[r0 * I_ + j] = __float2half_rn(v0);
                oh[r1 * I_ + j] = __float2half_rn(v1);
            } else {
                size_t i0 = r0 * N + n;
                size_t i1 = r1 * N + n;
                float2 v0 = make_float2(acc[mt][nt][0], acc[mt][nt][1]);
                float2 v1 = make_float2(acc[mt][nt][2], acc[mt][nt][3]);
                if (MODE == 1) {
                    float2 q0 = *(const float2*)(R + i0);
                    float2 q1 = *(const float2*)(R + i1);
                    v0.x += q0.x; v0.y += q0.y;
                    v1.x += q1.x; v1.y += q1.y;
                }
                *(float2*)(C + i0) = v0;
                *(float2*)(C + i1) = v1;
            }
        }
    }
}

// ----------------------------------------------------------------------------
// Embedding gather
// ----------------------------------------------------------------------------
__global__ void embed_kernel(const int* __restrict__ ids,
                             const float* __restrict__ emb,
                             float* __restrict__ h)
{
    int t = blockIdx.x;
    int id = ids[t];
    const float4* src = (const float4*)(emb + (size_t)id * H_);
    float4* dst = (float4*)(h + (size_t)t * H_);
    for (int i = threadIdx.x; i < H_ / 4; i += blockDim.x) dst[i] = src[i];
}

// ----------------------------------------------------------------------------
// RMSNorm -> bf16 (hi, lo)
// ----------------------------------------------------------------------------
__global__ void rmsnorm_kernel(const float* __restrict__ h,
                               const float* __restrict__ w,
                               __nv_bfloat16* __restrict__ xh,
                               __nv_bfloat16* __restrict__ xl)
{
    int t = blockIdx.x;
    const float* hr = h + (size_t)t * H_;
    __shared__ float red[256];
    float s = 0.f;
    for (int i = threadIdx.x; i < H_; i += 256) { float v = hr[i]; s += v * v; }
    red[threadIdx.x] = s; __syncthreads();
    for (int st = 128; st > 0; st >>= 1) {
        if (threadIdx.x < st) red[threadIdx.x] += red[threadIdx.x + st];
        __syncthreads();
    }
    float scale = rsqrtf(red[0] / (float)H_ + 1e-5f);
    for (int i = threadIdx.x; i < H_; i += 256) {
        float v = hr[i] * scale * w[i];
        __nv_bfloat16 hi, lo; split_bf16(v, hi, lo);
        xh[(size_t)t * H_ + i] = hi;
        xl[(size_t)t * H_ + i] = lo;
    }
}

// RMSNorm -> fp16 (hi, lo)
__global__ void rmsnorm_fp16_kernel(const float* __restrict__ h,
                                    const float* __restrict__ w,
                                    __half* __restrict__ xh,
                                    __half* __restrict__ xl)
{
    int t = blockIdx.x;
    const float* hr = h + (size_t)t * H_;
    __shared__ float red[256];
    float s = 0.f;
    for (int i = threadIdx.x; i < H_; i += 256) { float v = hr[i]; s += v * v; }
    red[threadIdx.x] = s; __syncthreads();
    for (int st = 128; st > 0; st >>= 1) {
        if (threadIdx.x < st) red[threadIdx.x] += red[threadIdx.x + st];
        __syncthreads();
    }
    float scale = rsqrtf(red[0] / (float)H_ + 1e-5f);
    for (int i = threadIdx.x; i < H_; i += 256) {
        float v = hr[i] * scale * w[i];
        __half hi, lo; split_fp16(v, hi, lo);
        xh[(size_t)t * H_ + i] = hi;
        xl[(size_t)t * H_ + i] = lo;
    }
}

// ----------------------------------------------------------------------------
// Q/K prep: fused RoPE + Q-scale + bf16 hi/lo split
// ----------------------------------------------------------------------------
__global__ void qkprep_kernel(const float* __restrict__ qkv, const int* __restrict__ pos,
                              __nv_bfloat16* __restrict__ Qh, __nv_bfloat16* __restrict__ Ql,
                              __nv_bfloat16* __restrict__ Kh, __nv_bfloat16* __restrict__ Kl)
{
    int idx = blockIdx.x * blockDim.x + threadIdx.x;
    if (idx >= T_ * 24 * 64) return;
    int i    = idx & 63;
    int head = (idx >> 6) % 24;
    int t    = idx / (24 * 64);
    int b = t / S_, s = t % S_;

    float p = (float)pos[t];
    float e = ((float)i / 64.0f) * 13.28771237954945f;  // log2(10000)
    float inv = exp2f(-e);
    float ang = p * inv;
    float sn, cs;
    sincosf(ang, &sn, &cs);

    int off = (head < NH_) ? head * HD_ : KOFF_ + (head - NH_) * HD_;
    const float* v = qkv + (size_t)t * QKVN_ + off;
    float x1 = v[i], x2 = v[i + 64];
    float r1 = x1 * cs - x2 * sn;
    float r2 = x2 * cs + x1 * sn;

    __nv_bfloat16 *dh, *dl;
    if (head < NH_) {
        const float scale = 0.08838834764831845f;
        r1 *= scale; r2 *= scale;
        size_t base = (((size_t)(b * NH_ + head)) * S_ + s) * HD_;
        dh = Qh + base; dl = Ql + base;
    } else {
        size_t base = (((size_t)(b * NKV_ + head - NH_)) * S_ + s) * HD_;
        dh = Kh + base; dl = Kl + base;
    }
    __nv_bfloat16 h1, l1, h2, l2;
    split_bf16(r1, h1, l1);
    split_bf16(r2, h2, l2);
    dh[i] = h1;      dl[i] = l1;
    dh[i + 64] = h2; dl[i + 64] = l2;
}

// ----------------------------------------------------------------------------
// V prep: transpose to [B][NKV][HD][S] + bf16 hi/lo split
// ----------------------------------------------------------------------------
__global__ void vprep_kernel(const float* __restrict__ qkv,
                             __nv_bfloat16* __restrict__ Vth,
                             __nv_bfloat16* __restrict__ Vtl)
{
    __shared__ float tile[32][33];
    const int z = blockIdx.z;
    const int b = z / NKV_, hkv = z % NKV_;
    const int s0 = blockIdx.x * 32, d0 = blockIdx.y * 32;
    const int tx = threadIdx.x, ty = threadIdx.y;
#pragma unroll
    for (int r = ty; r < 32; r += 8)
        tile[r][tx] = qkv[(size_t)(b * S_ + s0 + r) * QKVN_ + VOFF_ + hkv * HD_ + d0 + tx];
    __syncthreads();
    size_t base = ((size_t)(b * NKV_ + hkv)) * HD_ * S_;
#pragma unroll
    for (int r = ty; r < 32; r += 8) {
        float v = tile[tx][r];
        __nv_bfloat16 hi, lo; split_bf16(v, hi, lo);
        size_t idx = base + (size_t)(d0 + r) * S_ + s0 + tx;
        Vth[idx] = hi;
        Vtl[idx] = lo;
    }
}

// ----------------------------------------------------------------------------
// Flash attention (validated R5 kernel, unchanged)
// ----------------------------------------------------------------------------
__global__ __launch_bounds__(128)
void flash_kernel(const __nv_bfloat16* __restrict__ Qh, const __nv_bfloat16* __restrict__ Ql,
                  const __nv_bfloat16* __restrict__ Kh, const __nv_bfloat16* __restrict__ Kl,
                  const __nv_bfloat16* __restrict__ Vth, const __nv_bfloat16* __restrict__ Vtl,
                  __nv_bfloat16* __restrict__ Oh, __nv_bfloat16* __restrict__ Ol)
{
    extern __shared__ uint32_t sm[];
    uint32_t* KsH = sm;
    uint32_t* KsL = sm + 4096;
    uint32_t* VsH = sm + 8192;
    uint32_t* VsL = sm + 12288;

    const int qt = (int)gridDim.x - 1 - (int)blockIdx.x;
    const int z  = blockIdx.y;
    const int b  = z >> 4, hq = z & 15, hkv = hq >> 1;

    const int tid  = threadIdx.x;
    const int lane = tid & 31;
    const int w    = tid >> 5;
    const int g    = lane >> 2;
    const int tg   = lane & 3;

    uint32_t qFh[8][4], qFl[8][4];
    {
        const uint32_t* qbh = (const uint32_t*)(Qh + (((size_t)(b * NH_ + hq)) * S_ + qt * 64 + w * 16) * HD_);
        const uint32_t* qbl = (const uint32_t*)(Ql + (((size_t)(b * NH_ + hq)) * S_ + qt * 64 + w * 16) * HD_);
#pragma unroll
        for (int ks = 0; ks < 8; ks++) {
            int c = 8 * ks + tg;
            qFh[ks][0] = qbh[g * 64 + c];
            qFh[ks][1] = qbh[(g + 8) * 64 + c];
            qFh[ks][2] = qbh[g * 64 + c + 4];
            qFh[ks][3] = qbh[(g + 8) * 64 + c + 4];
            qFl[ks][0] = qbl[g * 64 + c];
            qFl[ks][1] = qbl[(g + 8) * 64 + c];
            qFl[ks][2] = qbl[g * 64 + c + 4];
            qFl[ks][3] = qbl[(g + 8) * 64 + c + 4];
        }
    }

    float oAcc[16][4];
#pragma unroll
    for (int i = 0; i < 16; i++)
#pragma unroll
        for (int j = 0; j < 4; j++) oAcc[i][j] = 0.f;
    float mA = -1e30f, mB = -1e30f, lA = 0.f, lB = 0.f;

    const __nv_bfloat16* KgH = Kh  + ((size_t)(b * NKV_ + hkv)) * S_ * HD_;
    const __nv_bfloat16* KgL = Kl  + ((size_t)(b * NKV_ + hkv)) * S_ * HD_;
    const __nv_bfloat16* VgH = Vth + ((size_t)(b * NKV_ + hkv)) * HD_ * S_;
    const __nv_bfloat16* VgL = Vtl + ((size_t)(b * NKV_ + hkv)) * HD_ * S_;

    for (int kt = 0; kt <= qt; kt++) {
#pragma unroll
        for (int p = 0; p < 8; p++) {
            int i = tid + p * 128;
            int r = i >> 4, cc = i & 15;
            int dst = r * 64 + ((cc ^ (r & 7)) << 2);
            cpa16(KsH + dst, KgH + (size_t)(kt * 64 + r) * HD_ + cc * 8);
            cpa16(KsL + dst, KgL + (size_t)(kt * 64 + r) * HD_ + cc * 8);
        }
#pragma unroll
        for (int p = 0; p < 8; p++) {
            int i = tid + p * 128;
            int n = i >> 3, cc = i & 7;
            int dst = n * 32 + ((cc ^ (n & 7)) << 2);
            cpa16(VsH + dst, VgH + (size_t)n * S_ + kt * 64 + cc * 8);
            cpa16(VsL + dst, VgL + (size_t)n * S_ + kt * 64 + cc * 8);
        }
        cp_commit();
        cp_wait<0>();
        __syncthreads();

        float sAcc[8][4];
#pragma unroll
        for (int i = 0; i < 8; i++)
#pragma unroll
            for (int j = 0; j < 4; j++) sAcc[i][j] = 0.f;

#pragma unroll
        for (int ks = 0; ks < 8; ks++) {
            uint32_t kFh[8][2], kFl[8][2];
            const int c0 = 8 * ks + tg;
#pragma unroll
            for (int nt = 0; nt < 8; nt++) {
                int key = nt * 8 + g;
                int sw = (key & 7) << 2;
                int o0 = key * 64 + (c0 ^ sw);
                int o1 = key * 64 + ((c0 + 4) ^ sw);
                kFh[nt][0] = KsH[o0]; kFh[nt][1] = KsH[o1];
                kFl[nt][0] = KsL[o0]; kFl[nt][1] = KsL[o1];
            }
#pragma unroll
            for (int nt = 0; nt < 8; nt++) {
                mma_bf16(sAcc[nt], qFh[ks][0], qFh[ks][1], qFh[ks][2], qFh[ks][3],
                         kFh[nt][0], kFh[nt][1]);
                mma_bf16(sAcc[nt], qFh[ks][0], qFh[ks][1], qFh[ks][2], qFh[ks][3],
                         kFl[nt][0], kFl[nt][1]);
                mma_bf16(sAcc[nt], qFl[ks][0], qFl[ks][1], qFl[ks][2], qFl[ks][3],
                         kFh[nt][0], kFh[nt][1]);
            }
        }

        if (kt == qt) {
            const int qrA = w * 16 + g, qrB = qrA + 8;
#pragma unroll
            for (int nt = 0; nt < 8; nt++) {
                int k0 = nt * 8 + 2 * tg, k1 = k0 + 1;
                if (k0 > qrA) sAcc[nt][0] = -1e30f;
                if (k1 > qrA) sAcc[nt][1] = -1e30f;
                if (k0 > qrB) sAcc[nt][2] = -1e30f;
                if (k1 > qrB) sAcc[nt][3] = -1e30f;
            }
        }

        float tmA = -1e30f, tmB = -1e30f;
#pragma unroll
        for (int nt = 0; nt < 8; nt++) {
            tmA = fmaxf(tmA, fmaxf(sAcc[nt][0], sAcc[nt][1]));
            tmB = fmaxf(tmB, fmaxf(sAcc[nt][2], sAcc[nt][3]));
        }
        tmA = fmaxf(tmA, __shfl_xor_sync(0xffffffff, tmA, 1));
        tmA = fmaxf(tmA, __shfl_xor_sync(0xffffffff, tmA, 2));
        tmB = fmaxf(tmB, __shfl_xor_sync(0xffffffff, tmB, 1));
        tmB = fmaxf(tmB, __shfl_xor_sync(0xffffffff, tmB, 2));
        float nmA = fmaxf(mA, tmA), nmB = fmaxf(mB, tmB);
        float eA = __expf(mA - nmA), eB = __expf(mB - nmB);

        float rsA = 0.f, rsB = 0.f;
#pragma unroll
        for (int nt = 0; nt < 8; nt++) {
            sAcc[nt][0] = __expf(sAcc[nt][0] - nmA);
            sAcc[nt][1] = __expf(sAcc[nt][1] - nmA);
            sAcc[nt][2] = __expf(sAcc[nt][2] - nmB);
            sAcc[nt][3] = __expf(sAcc[nt][3] - nmB);
            rsA += sAcc[nt][0] + sAcc[nt][1];
            rsB += sAcc[nt][2] + sAcc[nt][3];
        }
        rsA += __shfl_xor_sync(0xffffffff, rsA, 1);
        rsA += __shfl_xor_sync(0xffffffff, rsA, 2);
        rsB += __shfl_xor_sync(0xffffffff, rsB, 1);
        rsB += __shfl_xor_sync(0xffffffff, rsB, 2);
        lA = lA * eA + rsA;
        lB = lB * eB + rsB;
        mA = nmA; mB = nmB;
#pragma unroll
        for (int nt = 0; nt < 16; nt++) {
            oAcc[nt][0] *= eA; oAcc[nt][1] *= eA;
            oAcc[nt][2] *= eB; oAcc[nt][3] *= eB;
        }

#pragma unroll
        for (int ks2 = 0; ks2 < 4; ks2++) {
            uint32_t ph[4], pl[4];
#pragma unroll
            for (int q = 0; q < 2; q++) {
                const float* s4 = sAcc[2 * ks2 + q];
                uint32_t hp0 = pack_bf16x2(s4[0], s4[1]);
                uint32_t hp1 = pack_bf16x2(s4[2], s4[3]);
                float h00 = __uint_as_float(hp0 << 16);
                float h01 = __uint_as_float(hp0 & 0xFFFF0000u);
                float h10 = __uint_as_float(hp1 << 16);
                float h11 = __uint_as_float(hp1 & 0xFFFF0000u);
                ph[2 * q]     = hp0;
                ph[2 * q + 1] = hp1;
                pl[2 * q]     = pack_bf16x2(s4[0] - h00, s4[1] - h01);
                pl[2 * q + 1] = pack_bf16x2(s4[2] - h10, s4[3] - h11);
            }
            const int kp = 8 * ks2 + tg;
#pragma unroll
            for (int nt2 = 0; nt2 < 16; nt2++) {
                int n = nt2 * 8 + g;
                int sw = (n & 7) << 2;
                int o0 = n * 32 + (kp ^ sw);
                int o1 = n * 32 + ((kp + 4) ^ sw);
                uint32_t v0h = VsH[o0], v1h = VsH[o1];
                uint32_t v0l = VsL[o0], v1l = VsL[o1];
                mma_bf16(oAcc[nt2], ph[0], ph[1], ph[2], ph[3], v0h, v1h);
                mma_bf16(oAcc[nt2], ph[0], ph[1], ph[2], ph[3], v0l, v1l);
                mma_bf16(oAcc[nt2], pl[0], pl[1], pl[2], pl[3], v0h, v1h);
            }
        }
        __syncthreads();
    }

    const float ilA = 1.f / lA, ilB = 1.f / lB;
    const size_t tA = (size_t)b * S_ + qt * 64 + w * 16 + g;
    const size_t tB = tA + 8;
#pragma unroll
    for (int nt2 = 0; nt2 < 16; nt2++) {
        int col = hq * HD_ + nt2 * 8 + 2 * tg;
        float a0 = oAcc[nt2][0] * ilA, a1 = oAcc[nt2][1] * ilA;
        float b0 = oAcc[nt2][2] * ilB, b1 = oAcc[nt2][3] * ilB;

        uint32_t ahp = pack_bf16x2(a0, a1);
        uint32_t bhp = pack_bf16x2(b0, b1);
        float ah0 = __uint_as_float(ahp << 16), ah1 = __uint_as_float(ahp & 0xFFFF0000u);
        float bh0 = __uint_as_float(bhp << 16), bh1 = __uint_as_float(bhp & 0xFFFF0000u);
        uint32_t alp = pack_bf16x2(a0 - ah0, a1 - ah1);
        uint32_t blp = pack_bf16x2(b0 - bh0, b1 - bh1);

        *(uint32_t*)(Oh + tA * H_ + col) = ahp;
        *(uint32_t*)(Ol + tA * H_ + col) = alp;
        *(uint32_t*)(Oh + tB * H_ + col) = bhp;
        *(uint32_t*)(Ol + tB * H_ + col) = blp;
    }
}

// ----------------------------------------------------------------------------
// Host orchestration
// ----------------------------------------------------------------------------
extern "C" void kernel_launch(void* const* d_in, const int* in_sizes, int n_in,
                              void* d_out, int out_size)
{
    (void)in_sizes; (void)n_in; (void)out_size;
    const int*   ids    = (const int*)  d_in[0];
    const int*   pos    = (const int*)  d_in[1];
    const float* emb    = (const float*)d_in[2];
    const float* Wqkv   = (const float*)d_in[3];
    const float* Wo     = (const float*)d_in[4];
    const float* Wgu    = (const float*)d_in[5];
    const float* Wdn    = (const float*)d_in[6];
    const float* ln1    = (const float*)d_in[7];
    const float* ln2    = (const float*)d_in[8];
    const float* normw  = (const float*)d_in[9];
    const float* lmhead = (const float*)d_in[10];
    float* out = (float*)d_out;

    cudaFuncSetAttribute(tg_kernel<0>, cudaFuncAttributeMaxDynamicSharedMemorySize, TG_SMEM);
    cudaFuncSetAttribute(tg_kernel<1>, cudaFuncAttributeMaxDynamicSharedMemorySize, TG_SMEM);
    cudaFuncSetAttribute((const void*)tgf_kernel<0,1,1>, cudaFuncAttributeMaxDynamicSharedMemorySize, TGF_SMEM);
    cudaFuncSetAttribute((const void*)tgf_kernel<1,0,1>, cudaFuncAttributeMaxDynamicSharedMemorySize, TGF_SMEM);
    cudaFuncSetAttribute((const void*)tgf_kernel<2,0,1>, cudaFuncAttributeMaxDynamicSharedMemorySize, TGF_SMEM);
    cudaFuncSetAttribute(flash_kernel, cudaFuncAttributeMaxDynamicSharedMemorySize, 65536);

    float *h, *qkv;
    __nv_bfloat16 *x, *xl, *attn, *attnl, *si, *wh, *wl;
    __nv_bfloat16 *qh, *ql, *kh, *kl, *vth, *vtl;
    cudaGetSymbolAddress((void**)&h,     g_h);
    cudaGetSymbolAddress((void**)&x,     g_x);
    cudaGetSymbolAddress((void**)&xl,    g_xl);
    cudaGetSymbolAddress((void**)&qkv,   g_qkv);
    cudaGetSymbolAddress((void**)&attn,  g_attn);
    cudaGetSymbolAddress((void**)&attnl, g_attnl);
    cudaGetSymbolAddress((void**)&si,    g_si);
    cudaGetSymbolAddress((void**)&wh,    g_wh);
    cudaGetSymbolAddress((void**)&wl,    g_wl);
    cudaGetSymbolAddress((void**)&qh,    g_qh);
    cudaGetSymbolAddress((void**)&ql,    g_ql);
    cudaGetSymbolAddress((void**)&kh,    g_kh);
    cudaGetSymbolAddress((void**)&kl,    g_kl);
    cudaGetSymbolAddress((void**)&vth,   g_vth);
    cudaGetSymbolAddress((void**)&vtl,   g_vtl);

    embed_kernel<<<T_, 256>>>(ids, emb, h);

    for (int l = 0; l < L_; l++) {
        const float* wqkv = Wqkv + (size_t)l * H_ * QKVN_;
        const float* wo   = Wo   + (size_t)l * H_ * H_;
        const float* wgu  = Wgu  + (size_t)l * H_ * (2 * I_);
        const float* wdn  = Wdn  + (size_t)l * I_ * H_;

        // ---- attention block (bf16 3-MMA, validated) ----
        rmsnorm_kernel<<<T_, 256>>>(h, ln1 + (size_t)l * H_, x, xl);
        wsplit_t_kernel<<<dim3(QKVN_ / 32, H_ / 64), dim3(32, 8)>>>(wqkv, wh, wl, H_, QKVN_, 0, 1, 0);
        tg_kernel<0><<<dim3(QKVN_ / 128, T_ / 64), 128, TG_SMEM>>>(x, xl, wh, wl, nullptr, qkv,
                                                                   T_, QKVN_, H_);

        {
            int tot = T_ * 24 * 64;
            qkprep_kernel<<<(tot + 255) / 256, 256>>>(qkv, pos, qh, ql, kh, kl);
        }
        vprep_kernel<<<dim3(S_ / 32, HD_ / 32, B_ * NKV_), dim3(32, 8)>>>(qkv, vth, vtl);

        flash_kernel<<<dim3(S_ / 64, B_ * NH_), 128, 65536>>>(qh, ql, kh, kl, vth, vtl,
                                                              attn, attnl);

        wsplit_t_kernel<<<dim3(H_ / 32, H_ / 64), dim3(32, 8)>>>(wo, wh, wl, H_, H_, 0, 1, 0);
        tg_kernel<1><<<dim3(H_ / 128, T_ / 64), 128, TG_SMEM>>>(attn, attnl, wh, wl, h, h,
                                                                T_, H_, H_);

        // ---- MLP block (fp16; gate-up 1-MMA, down-proj 1-MMA) ----
        rmsnorm_fp16_kernel<<<T_, 256>>>(h, ln2 + (size_t)l * H_, (__half*)x, (__half*)xl);
        // merged gate/up staging: z=0 -> gate cols (rows 2j), z=1 -> up cols (rows 2j+1)
        wsplit_t_fp16_kernel<<<dim3(I_ / 32, H_ / 64, 2), dim3(32, 8)>>>(
            wgu, (__half*)wh, H_, 2 * I_, 0, 2, 0, I_, 1);
        tgf_kernel<2, 0, 1><<<dim3(2 * I_ / 128, T_ / 64), 128, TGF_SMEM>>>(
            (const __half*)x, nullptr, (const __half*)wh,
            nullptr, nullptr, (__half*)si, T_, 2 * I_, H_);

        wsplit_t_fp16_kernel<<<dim3(H_ / 32, I_ / 64, 1), dim3(32, 8)>>>(
            wdn, (__half*)wh, I_, H_, 0, 1, 0, 0, 0);
        tgf_kernel<1, 0, 1><<<dim3(H_ / 128, T_ / 64), 128, TGF_SMEM>>>(
            (const __half*)si, nullptr, (const __half*)wh,
            h, h, nullptr, T_, H_, I_);
    }

    // ---- final norm + fully-fp16 1-MMA lm_head (M-fastest: stream 128MB B once) ----
    rmsnorm_fp16_kernel<<<T_, 256>>>(h, normw, (__half*)x, (__half*)xl);
    wsplit_t_fp16_kernel<<<dim3(VOCAB_ / 32, H_ / 64, 1), dim3(32, 8)>>>(
        lmhead, (__half*)wh, H_, VOCAB_, 0, 1, 0, 0, 0);
    tgf_kernel<0, 1, 1><<<dim3(T_ / 64, VOCAB_ / 128), 128, TGF_SMEM>>>(
        (const __half*)x, (const __half*)xl, (const __half*)wh,
        nullptr, out, nullptr, T_, VOCAB_, H_);
}